// round 6
// baseline (speedup 1.0000x reference)
#include <cuda_runtime.h>
#include <cuda_bf16.h>
#include <cstdint>
#include <math.h>

// ---------------- problem constants ----------------
constexpr int BSZ   = 2048;
constexpr int VIEWS = 2;
constexpr int DIM   = 512;
constexpr int NTOT  = BSZ * VIEWS;          // 4096
constexpr float TEMP = 0.07f;
constexpr float RSQRT2PI = 0.3989422804014327f;

// GEMM tiling: 128x128 CTA tile, 8 warps of 64x32, K-chunks of 32
constexpr int KC = 32;
constexpr int NCHUNK = DIM / KC;             // 16
constexpr int LDB = 80;                      // smem row stride bytes (64B data + 16B pad)
constexpr int OPB = 128 * LDB;               // 10240 B per operand tile
constexpr int STG = 4 * OPB;                 // Ahi|Alo|Bhi|Blo = 40960 B per stage
constexpr int DSMEM = 2 * STG;               // 81920 B  -> 2 CTAs/SM

// ---------------- device scratch --------------------
__device__ __align__(16) __nv_bfloat16 g_Fhi[(size_t)NTOT * DIM];   // 4 MB
__device__ __align__(16) __nv_bfloat16 g_Flo[(size_t)NTOT * DIM];   // 4 MB
// packed tables: high16 = mask bf16, low16 = delta u16
__device__ __align__(16) unsigned g_cmb [(size_t)BSZ * BSZ];        // [i][j]: mask_ij | delta_ij
__device__ __align__(16) unsigned g_cmbT[(size_t)BSZ * BSZ];        // [i][j]: mask_ij | delta_ji
__device__ float g_S[BSZ];
__device__ float g_sorted[BSZ];
__device__ float g_u[NTOT];
__device__ float g_p[NTOT];

// ---------------- PTX helpers -----------------------
__device__ __forceinline__ uint32_t smem_u32(const void* p) {
    uint32_t a;
    asm("{ .reg .u64 t; cvta.to.shared.u64 t, %1; cvt.u32.u64 %0, t; }" : "=r"(a) : "l"(p));
    return a;
}
__device__ __forceinline__ void cpa16(uint32_t d, const void* s) {
    asm volatile("cp.async.cg.shared.global [%0], [%1], 16;" :: "r"(d), "l"(s) : "memory");
}
#define CP_COMMIT() asm volatile("cp.async.commit_group;" ::: "memory")
#define CP_WAIT0()  asm volatile("cp.async.wait_group 0;" ::: "memory")
#define CP_WAIT1()  asm volatile("cp.async.wait_group 1;" ::: "memory")
__device__ __forceinline__ void ldsm4(uint32_t* r, uint32_t a) {
    asm volatile("ldmatrix.sync.aligned.m8n8.x4.shared.b16 {%0,%1,%2,%3}, [%4];"
        : "=r"(r[0]), "=r"(r[1]), "=r"(r[2]), "=r"(r[3]) : "r"(a));
}
__device__ __forceinline__ void mma_bf16(float* c,
    uint32_t a0, uint32_t a1, uint32_t a2, uint32_t a3, uint32_t b0, uint32_t b1) {
    asm volatile("mma.sync.aligned.m16n8k16.row.col.f32.bf16.bf16.f32 "
        "{%0,%1,%2,%3}, {%4,%5,%6,%7}, {%8,%9}, {%0,%1,%2,%3};"
        : "+f"(c[0]), "+f"(c[1]), "+f"(c[2]), "+f"(c[3])
        : "r"(a0), "r"(a1), "r"(a2), "r"(a3), "r"(b0), "r"(b1));
}

// ---------------- K0: bf16 hi/lo split + zero accums -------------------------
__global__ void k_prep(const float* __restrict__ feats) {
    int idx = blockIdx.x * blockDim.x + threadIdx.x;   // 262144 = 4096 rows * 64 groups
    int row = idx >> 6;
    int c0  = (idx & 63) * 8;
    int b = row & (BSZ - 1), v = row >> 11;
    const float* src = feats + ((size_t)(b * VIEWS + v) * DIM + c0);
    float4 f0 = *(const float4*)src;
    float4 f1 = *(const float4*)(src + 4);
    float vals[8] = {f0.x, f0.y, f0.z, f0.w, f1.x, f1.y, f1.z, f1.w};
    __nv_bfloat16 hi[8], lo[8];
#pragma unroll
    for (int e = 0; e < 8; e++) {
        hi[e] = __float2bfloat16(vals[e]);
        lo[e] = __float2bfloat16(vals[e] - __bfloat162float(hi[e]));
    }
    size_t dst = (size_t)row * DIM + c0;
    *(uint4*)&g_Fhi[dst] = *(const uint4*)hi;
    *(uint4*)&g_Flo[dst] = *(const uint4*)lo;
    if (idx < NTOT) { g_u[idx] = 0.f; g_p[idx] = 0.f; }
}

// ---------------- K1: bitonic sort of labels ---------------------------------
__global__ void k_sort(const float* __restrict__ labels) {
    __shared__ float s[BSZ];
    int tid = threadIdx.x;
    s[tid] = labels[tid]; s[tid + 1024] = labels[tid + 1024];
    __syncthreads();
    for (int k = 2; k <= BSZ; k <<= 1)
        for (int j = k >> 1; j > 0; j >>= 1) {
            for (int i = tid; i < BSZ; i += 1024) {
                int ixj = i ^ j;
                if (ixj > i) {
                    bool up = ((i & k) == 0);
                    float a = s[i], bb = s[ixj];
                    if ((a > bb) == up) { s[i] = bb; s[ixj] = a; }
                }
            }
            __syncthreads();
        }
    g_sorted[tid] = s[tid]; g_sorted[tid + 1024] = s[tid + 1024];
}

// ---------------- K2: packed (mask, delta^T) table + S row sums --------------
// block = row CENTER jb; per target ib:  cnt = #{k : (c-l_k)^2 <= (c-l_ib)^2}
// Writes g_cmbT[jb][ib] = (mask(jb,ib) bf16 << 16) | delta[ib][jb] u16.
__global__ void k_tab(const float* __restrict__ labels) {
    __shared__ float s[BSZ];
    __shared__ float red[256];
    int tid = threadIdx.x;
    int jb  = blockIdx.x;
    for (int m = tid; m < BSZ; m += 256) s[m] = g_sorted[m];
    __syncthreads();
    float c = labels[jb];
    // iC: first index with s[m] >= c (hoisted; c exists in the array)
    int lo = 0, hi = BSZ;
    while (lo < hi) { int mid = (lo + hi) >> 1; if (s[mid] < c) lo = mid + 1; else hi = mid; }
    int iC = lo;
    float rs = 0.f;
    for (int ib = tid; ib < BSZ; ib += 256) {
        float li = labels[ib];
        float dl = c - li;
        float t2 = dl * dl;
        float m  = expf(-0.5f * t2) * RSQRT2PI;
        rs += m;
        // two independent window searches (ILP)
        int l0 = 0, l1 = iC;
        int r0 = iC, r1 = BSZ - 1;
#pragma unroll 1
        while (l0 < l1 || r0 < r1) {
            if (l0 < l1) { int mid = (l0 + l1) >> 1; float d = c - s[mid];
                           if (d * d <= t2) l1 = mid; else l0 = mid + 1; }
            if (r0 < r1) { int mid = (r0 + r1 + 1) >> 1; float d = s[mid] - c;
                           if (d * d <= t2) r0 = mid; else r1 = mid - 1; }
        }
        int cnt = r0 - l0 + 1;
        unsigned dlt = (unsigned)(VIEWS * (BSZ - cnt));
        unsigned mb  = (unsigned)__bfloat16_as_ushort(__float2bfloat16(m));
        g_cmbT[(size_t)jb * BSZ + ib] = (mb << 16) | dlt;
    }
    red[tid] = rs; __syncthreads();
    for (int st = 128; st > 0; st >>= 1) { if (tid < st) red[tid] += red[tid + st]; __syncthreads(); }
    if (tid == 0) g_S[jb] = (float)VIEWS * red[0] - RSQRT2PI;
}

// ---------------- K2b: transpose packed table (u32, 64x64 tiles) -------------
// tile row stride = 68 words = 272 B = 17*16 -> uint4-aligned rows (fix for
// round-5 misaligned-address fault caused by the 65-word stride).
__global__ void k_transp() {
    __shared__ __align__(16) unsigned tile[64][68];
    int bx = blockIdx.x & 31, by = blockIdx.x >> 5;
    int r  = threadIdx.x >> 2;
    int c0 = (threadIdx.x & 3) * 16;
    const unsigned* src = g_cmbT + (size_t)(by * 64 + r) * BSZ + bx * 64 + c0;
#pragma unroll
    for (int q = 0; q < 4; q++)
        *(uint4*)&tile[r][c0 + q * 4] = *(const uint4*)(src + q * 4);
    __syncthreads();
    unsigned ov[16];
#pragma unroll
    for (int k = 0; k < 16; k++) ov[k] = tile[c0 + k][r];
    unsigned* dst = g_cmb + (size_t)(bx * 64 + r) * BSZ + by * 64 + c0;
#pragma unroll
    for (int q = 0; q < 4; q++)
        *(uint4*)(dst + q * 4) = *(const uint4*)(ov + q * 4);
}

// ---------------- K3: mma.sync bf16x3 GEMM + fused epilogue ------------------
__global__ __launch_bounds__(256, 2) void k_main() {
    extern __shared__ __align__(16) char smem[];
    __shared__ float uRow[128], pRow[128], uCol[128], pCol[128];
    uint32_t sb = smem_u32(smem);
    int tid = threadIdx.x, wid = tid >> 5, lane = tid & 31;

    // triangular tile index
    int t  = blockIdx.x;
    int bi = (int)((sqrtf(8.f * (float)t + 1.f) - 1.f) * 0.5f);
    while ((bi + 1) * (bi + 2) / 2 <= t) bi++;
    while (bi * (bi + 1) / 2 > t) bi--;
    int bj = t - bi * (bi + 1) / 2;
    int i0 = bi * 128, j0 = bj * 128;
    bool diag = (bi == bj);

    if (tid < 128) { uRow[tid] = 0.f; pRow[tid] = 0.f; uCol[tid] = 0.f; pCol[tid] = 0.f; }

    int lr = tid >> 2, lch = tid & 3;      // cp.async: 4x16B per 64B row, 64 rows/pass
    auto issue = [&](int c) {
        uint32_t stg = sb + (uint32_t)(c & 1) * STG;
        int gco = c * KC + lch * 8;
#pragma unroll
        for (int rr = 0; rr < 2; rr++) {
            int row = rr * 64 + lr;
            uint32_t d = stg + (uint32_t)(row * LDB + lch * 16);
            cpa16(d,           &g_Fhi[(size_t)(i0 + row) * DIM + gco]);
            cpa16(d + OPB,     &g_Flo[(size_t)(i0 + row) * DIM + gco]);
            cpa16(d + 2 * OPB, &g_Fhi[(size_t)(j0 + row) * DIM + gco]);
            cpa16(d + 3 * OPB, &g_Flo[(size_t)(j0 + row) * DIM + gco]);
        }
        CP_COMMIT();
    };

    int wr = wid & 1, wc = wid >> 1;       // warp tile = 64 rows x 32 cols
    int arow = (lane & 7) + ((lane >> 3) & 1) * 8;
    int acol = ((lane >> 4) & 1) * 8;
    int brow = (lane & 7) + ((lane >> 4) & 1) * 8;
    int bcol = ((lane >> 3) & 1) * 8;

    float acc[4][4][4];
#pragma unroll
    for (int mt = 0; mt < 4; mt++)
#pragma unroll
        for (int nt = 0; nt < 4; nt++)
#pragma unroll
            for (int e = 0; e < 4; e++) acc[mt][nt][e] = 0.f;

    issue(0); issue(1);
    for (int c = 0; c < NCHUNK; c++) {
        if (c == NCHUNK - 1) { CP_WAIT0(); } else { CP_WAIT1(); }
        __syncthreads();
        uint32_t stg = sb + (uint32_t)(c & 1) * STG;
#pragma unroll
        for (int ks = 0; ks < 2; ks++) {
            int k0 = ks * 16;
            uint32_t ah[4][4], al[4][4], bh[2][4], bl[2][4];
#pragma unroll
            for (int mt = 0; mt < 4; mt++) {
                int row = wr * 64 + mt * 16 + arow;
                uint32_t ad = stg + (uint32_t)(row * LDB + (k0 + acol) * 2);
                ldsm4(ah[mt], ad);
                ldsm4(al[mt], ad + OPB);
            }
#pragma unroll
            for (int pr = 0; pr < 2; pr++) {
                int row = wc * 32 + pr * 16 + brow;
                uint32_t bd = stg + (uint32_t)(2 * OPB + row * LDB + (k0 + bcol) * 2);
                ldsm4(bh[pr], bd);
                ldsm4(bl[pr], bd + OPB);
            }
#pragma unroll
            for (int sp = 0; sp < 3; sp++) {
#pragma unroll
                for (int mt = 0; mt < 4; mt++) {
#pragma unroll
                    for (int nt = 0; nt < 4; nt++) {
                        int pr = nt >> 1, h2 = (nt & 1) * 2;
                        uint32_t a0, a1, a2, a3, b0, b1;
                        if (sp == 2) { a0 = al[mt][0]; a1 = al[mt][1]; a2 = al[mt][2]; a3 = al[mt][3]; }
                        else         { a0 = ah[mt][0]; a1 = ah[mt][1]; a2 = ah[mt][2]; a3 = ah[mt][3]; }
                        if (sp == 1) { b0 = bl[pr][h2]; b1 = bl[pr][h2 + 1]; }
                        else         { b0 = bh[pr][h2]; b1 = bh[pr][h2 + 1]; }
                        mma_bf16(acc[mt][nt], a0, a1, a2, a3, b0, b1);
                    }
                }
            }
        }
        __syncthreads();
        if (c + 2 < NCHUNK) issue(c + 2);
    }

    // ---- fused epilogue (table-driven mask + delta) ----
    const float invT = 1.0f / TEMP;
    float uR[8], pR[8], uC[8], pC[8];
#pragma unroll
    for (int e = 0; e < 8; e++) { uR[e] = 0.f; pR[e] = 0.f; uC[e] = 0.f; pC[e] = 0.f; }
    int rq = lane >> 2, cq = 2 * (lane & 3);
#pragma unroll
    for (int mt = 0; mt < 4; mt++) {
#pragma unroll
        for (int h = 0; h < 2; h++) {
            int r  = wr * 64 + mt * 16 + rq + h * 8;
            int iB = (i0 + r) & (BSZ - 1);
            const unsigned* crow  = g_cmb  + (size_t)iB * BSZ;
            const unsigned* cTrow = g_cmbT + (size_t)iB * BSZ;
            int ridx = mt * 2 + h;
#pragma unroll
            for (int nt = 0; nt < 4; nt++) {
                int c2  = wc * 32 + nt * 8 + cq;
                int jB2 = (j0 + c2) & (BSZ - 1);
                uint2 cp  = *(const uint2*)(crow  + jB2);
                uint2 cpT = *(const uint2*)(cTrow + jB2);
#pragma unroll
                for (int e = 0; e < 2; e++) {
                    int cc = c2 + e;
                    unsigned v  = e ? cp.y  : cp.x;
                    unsigned vT = e ? cpT.y : cpT.x;
                    float a  = acc[mt][nt][h * 2 + e];
                    float x  = fmaf(a, invT, -invT);
                    float m  = __uint_as_float(v & 0xFFFF0000u);
                    float d  = (float)(unsigned short)v;
                    float dT = (float)(unsigned short)vT;
                    float ex = __expf(x);
                    bool skip = diag && (r == cc);
                    if (!skip) {
                        uR[ridx] = fmaf(ex, d, uR[ridx]);
                        pR[ridx] = fmaf(m, x, pR[ridx]);
                        if (!diag) {
                            int cidx = nt * 2 + e;
                            uC[cidx] = fmaf(ex, dT, uC[cidx]);
                            pC[cidx] = fmaf(m, x, pC[cidx]);
                        }
                    }
                }
            }
        }
    }
#pragma unroll
    for (int mt = 0; mt < 4; mt++)
#pragma unroll
        for (int h = 0; h < 2; h++) {
            int r = wr * 64 + mt * 16 + rq + h * 8;
            atomicAdd(&uRow[r], uR[mt * 2 + h]);
            atomicAdd(&pRow[r], pR[mt * 2 + h]);
        }
    if (!diag) {
#pragma unroll
        for (int nt = 0; nt < 4; nt++)
#pragma unroll
            for (int e = 0; e < 2; e++) {
                int cc = wc * 32 + nt * 8 + cq + e;
                atomicAdd(&uCol[cc], uC[nt * 2 + e]);
                atomicAdd(&pCol[cc], pC[nt * 2 + e]);
            }
    }
    __syncthreads();
    if (tid < 128) {
        atomicAdd(&g_u[i0 + tid], uRow[tid]);
        atomicAdd(&g_p[i0 + tid], pRow[tid]);
        if (!diag) {
            atomicAdd(&g_u[j0 + tid], uCol[tid]);
            atomicAdd(&g_p[j0 + tid], pCol[tid]);
        }
    }
}

// ---------------- K4: final reduction -----------------------------------------
__global__ void k_final(float* __restrict__ out) {
    __shared__ float red[512];
    int tid = threadIdx.x;
    float sum = 0.f;
    for (int i = tid; i < NTOT; i += 512) {
        float lp = g_p[i] / g_S[i & (BSZ - 1)] - logf(g_u[i]);
        sum += lp;
    }
    red[tid] = sum; __syncthreads();
    for (int st = 256; st > 0; st >>= 1) { if (tid < st) red[tid] += red[tid + st]; __syncthreads(); }
    if (tid == 0) out[0] = -red[0] / (float)NTOT;
}

// ---------------- entry --------------------------------------------------------
extern "C" void kernel_launch(void* const* d_in, const int* in_sizes, int n_in,
                              void* d_out, int out_size) {
    (void)in_sizes; (void)n_in; (void)out_size;
    const float* feats  = (const float*)d_in[0];
    const float* labels = (const float*)d_in[1];
    float* out = (float*)d_out;

    cudaFuncSetAttribute(k_main, cudaFuncAttributeMaxDynamicSharedMemorySize, DSMEM);

    k_prep  <<<1024, 256>>>(feats);
    k_sort  <<<1, 1024>>>(labels);
    k_tab   <<<2048, 256>>>(labels);
    k_transp<<<1024, 256>>>();
    k_main  <<<528, 256, DSMEM>>>();
    k_final <<<1, 512>>>(out);
}

// round 7
// speedup vs baseline: 1.1961x; 1.1961x over previous
#include <cuda_runtime.h>
#include <cuda_bf16.h>
#include <cstdint>
#include <math.h>

// ---------------- problem constants ----------------
constexpr int BSZ   = 2048;
constexpr int VIEWS = 2;
constexpr int DIM   = 512;
constexpr int NTOT  = BSZ * VIEWS;          // 4096
constexpr float TEMP = 0.07f;
constexpr float RSQRT2PI = 0.3989422804014327f;

// GEMM tiling: 128x128 CTA tile, 8 warps of 64x32, tf32 m16n8k8, K-chunks of 32
constexpr int KC = 32;
constexpr int NCHUNK = DIM / KC;             // 16
constexpr int STAGE = 32768;                 // A 16K + B 16K per chunk
constexpr int NSTG = 3;
constexpr int DSMEM = NSTG * STAGE;          // 98304 B -> 2 CTAs/SM

// ---------------- device scratch --------------------
// fragment-major tf32 operand images (written by k_prep, consumed raw by cp.async)
// A blocks: [rowGroup 0..31][chunk 0..15][m16tile 0..7][slice 0..3][lane 0..31][4]
__device__ __align__(16) unsigned g_FA[16384 * 128];     // 8 MB
// B blocks: [colGroup 0..31][chunk 0..15][n8tile 0..15][slice 0..3][lane 0..31][2]
__device__ __align__(16) unsigned g_FB[32768 * 64];      // 8 MB
__device__ __align__(16) unsigned short g_dt [(size_t)BSZ * BSZ];   // delta[i][j], 8 MB
__device__ __align__(16) unsigned short g_dtT[(size_t)BSZ * BSZ];   // delta[j][i], 8 MB
__device__ float g_S[BSZ];
__device__ float g_sorted[BSZ];
__device__ float g_u[NTOT];
__device__ float g_p[NTOT];

// ---------------- PTX helpers -----------------------
__device__ __forceinline__ uint32_t smem_u32(const void* p) {
    uint32_t a;
    asm("{ .reg .u64 t; cvta.to.shared.u64 t, %1; cvt.u32.u64 %0, t; }" : "=r"(a) : "l"(p));
    return a;
}
__device__ __forceinline__ void cpa16(uint32_t d, const void* s) {
    asm volatile("cp.async.cg.shared.global [%0], [%1], 16;" :: "r"(d), "l"(s) : "memory");
}
#define CP_COMMIT() asm volatile("cp.async.commit_group;" ::: "memory")
#define CP_WAIT0()  asm volatile("cp.async.wait_group 0;" ::: "memory")
#define CP_WAIT1()  asm volatile("cp.async.wait_group 1;" ::: "memory")
__device__ __forceinline__ uint32_t to_tf32(float f) {
    uint32_t u;
    asm("cvt.rna.tf32.f32 %0, %1;" : "=r"(u) : "f"(f));
    return u;
}
__device__ __forceinline__ void mma_tf32(float* c, const uint32_t* a, const uint32_t* b) {
    asm volatile("mma.sync.aligned.m16n8k8.row.col.f32.tf32.tf32.f32 "
        "{%0,%1,%2,%3}, {%4,%5,%6,%7}, {%8,%9}, {%0,%1,%2,%3};"
        : "+f"(c[0]), "+f"(c[1]), "+f"(c[2]), "+f"(c[3])
        : "r"(a[0]), "r"(a[1]), "r"(a[2]), "r"(a[3]), "r"(b[0]), "r"(b[1]));
}

// ---------------- K0: tf32 convert + fragment-major scatter + zero accums ----
__device__ __forceinline__ float ld_feat(const float* feats, int row, int col) {
    int b = row & (BSZ - 1), v = row >> 11;
    return feats[(size_t)((b << 1) | v) * DIM + col];
}
__global__ void k_prep(const float* __restrict__ feats) {
    int tid = blockIdx.x * blockDim.x + threadIdx.x;   // 6144*256 = 1572864
    if (tid < NTOT) { g_u[tid] = 0.f; g_p[tid] = 0.f; }
    int gw = tid >> 5;           // warp id 0..49151
    int l  = tid & 31;
    if (gw < 16384) {
        // A block: s|t|chunk|rg
        int s = gw & 3, t = (gw >> 2) & 7, ch = (gw >> 5) & 15, rg = gw >> 9;
        int R = rg * 128 + t * 16 + (l >> 2);
        int C = ch * 32 + s * 8 + (l & 3);
        uint4 o;
        o.x = to_tf32(ld_feat(feats, R,     C));
        o.y = to_tf32(ld_feat(feats, R + 8, C));
        o.z = to_tf32(ld_feat(feats, R,     C + 4));
        o.w = to_tf32(ld_feat(feats, R + 8, C + 4));
        ((uint4*)g_FA)[(size_t)gw * 32 + l] = o;
    } else {
        int w2 = gw - 16384;
        int s = w2 & 3, n8 = (w2 >> 2) & 15, ch = (w2 >> 6) & 15, ng = w2 >> 10;
        int J = ng * 128 + n8 * 8 + (l >> 2);
        int K = ch * 32 + s * 8 + (l & 3);
        uint2 o;
        o.x = to_tf32(ld_feat(feats, J, K));
        o.y = to_tf32(ld_feat(feats, J, K + 4));
        ((uint2*)g_FB)[(size_t)w2 * 32 + l] = o;
    }
}

// ---------------- K1: bitonic sort of labels ---------------------------------
__global__ void k_sort(const float* __restrict__ labels) {
    __shared__ float s[BSZ];
    int tid = threadIdx.x;
    s[tid] = labels[tid]; s[tid + 1024] = labels[tid + 1024];
    __syncthreads();
    for (int k = 2; k <= BSZ; k <<= 1)
        for (int j = k >> 1; j > 0; j >>= 1) {
            for (int i = tid; i < BSZ; i += 1024) {
                int ixj = i ^ j;
                if (ixj > i) {
                    bool up = ((i & k) == 0);
                    float a = s[i], bb = s[ixj];
                    if ((a > bb) == up) { s[i] = bb; s[ixj] = a; }
                }
            }
            __syncthreads();
        }
    g_sorted[tid] = s[tid]; g_sorted[tid + 1024] = s[tid + 1024];
}

// ---------------- K2: delta^T table (uint16) + S row sums --------------------
__global__ void k_tab(const float* __restrict__ labels) {
    __shared__ float s[BSZ];
    __shared__ float red[256];
    int tid = threadIdx.x;
    int jb  = blockIdx.x;
    for (int m = tid; m < BSZ; m += 256) s[m] = g_sorted[m];
    __syncthreads();
    float c = labels[jb];
    int lo = 0, hi = BSZ;
    while (lo < hi) { int mid = (lo + hi) >> 1; if (s[mid] < c) lo = mid + 1; else hi = mid; }
    int iC = lo;
    float rs = 0.f;
    for (int ib = tid; ib < BSZ; ib += 256) {
        float li = labels[ib];
        float dl = c - li;
        float t2 = dl * dl;
        rs += expf(-0.5f * t2) * RSQRT2PI;
        int l0 = 0, l1 = iC;
        int r0 = iC, r1 = BSZ - 1;
#pragma unroll 1
        while (l0 < l1 || r0 < r1) {
            if (l0 < l1) { int mid = (l0 + l1) >> 1; float d = c - s[mid];
                           if (d * d <= t2) l1 = mid; else l0 = mid + 1; }
            if (r0 < r1) { int mid = (r0 + r1 + 1) >> 1; float d = s[mid] - c;
                           if (d * d <= t2) r0 = mid; else r1 = mid - 1; }
        }
        int cnt = r0 - l0 + 1;
        g_dtT[(size_t)jb * BSZ + ib] = (unsigned short)(VIEWS * (BSZ - cnt));
    }
    red[tid] = rs; __syncthreads();
    for (int st = 128; st > 0; st >>= 1) { if (tid < st) red[tid] += red[tid + st]; __syncthreads(); }
    if (tid == 0) g_S[jb] = (float)VIEWS * red[0] - RSQRT2PI;
}

// ---------------- K2b: transpose delta^T -> delta (ushort, proven R4) --------
__global__ void k_transp() {
    __shared__ unsigned short tile[64][72];
    int bx = blockIdx.x & 31, by = blockIdx.x >> 5;
    int r  = threadIdx.x >> 2;
    int c0 = (threadIdx.x & 3) * 16;
    const unsigned short* src = g_dtT + (size_t)(by * 64 + r) * BSZ + bx * 64 + c0;
    *(uint4*)&tile[r][c0]     = *(const uint4*)src;
    *(uint4*)&tile[r][c0 + 8] = *(const uint4*)(src + 8);
    __syncthreads();
    unsigned short ov[16];
#pragma unroll
    for (int k = 0; k < 16; k++) ov[k] = tile[c0 + k][r];
    unsigned short* dst = g_dt + (size_t)(bx * 64 + r) * BSZ + by * 64 + c0;
    *(uint4*)dst       = *(const uint4*)ov;
    *(uint4*)(dst + 8) = *(const uint4*)(ov + 8);
}

// ---------------- K3: tf32 mma.sync GEMM + fused epilogue --------------------
__global__ __launch_bounds__(256, 2) void k_main(const float* __restrict__ labels) {
    extern __shared__ __align__(16) char smem[];
    __shared__ float uRow[128], pRow[128], uCol[128], pCol[128];
    __shared__ float slabA[128], slabB[128];
    uint32_t sb = smem_u32(smem);
    int tid = threadIdx.x, wid = tid >> 5, lane = tid & 31;

    // triangular tile index
    int t  = blockIdx.x;
    int bi = (int)((sqrtf(8.f * (float)t + 1.f) - 1.f) * 0.5f);
    while ((bi + 1) * (bi + 2) / 2 <= t) bi++;
    while (bi * (bi + 1) / 2 > t) bi--;
    int bj = t - bi * (bi + 1) / 2;
    int i0 = bi * 128, j0 = bj * 128;
    bool diag = (bi == bj);

    if (tid < 128) {
        uRow[tid] = 0.f; pRow[tid] = 0.f; uCol[tid] = 0.f; pCol[tid] = 0.f;
        slabA[tid] = labels[(i0 + tid) & (BSZ - 1)];
        slabB[tid] = labels[(j0 + tid) & (BSZ - 1)];
    }

    const char* Ab = (const char*)g_FA + (size_t)(i0 >> 7) * 16 * 16384;
    const char* Bb = (const char*)g_FB + (size_t)(j0 >> 7) * 16 * 16384;

    auto issue = [&](int c, int si) {
        uint32_t stg = sb + (uint32_t)si * STAGE;
        const char* As = Ab + (size_t)c * 16384;
        const char* Bs = Bb + (size_t)c * 16384;
#pragma unroll
        for (int q = 0; q < 4; q++) {
            cpa16(stg + q * 4096 + tid * 16,          As + q * 4096 + tid * 16);
            cpa16(stg + 16384 + q * 4096 + tid * 16,  Bs + q * 4096 + tid * 16);
        }
        CP_COMMIT();
    };

    int wr = wid & 1, wc = wid >> 1;   // warp tile 64 rows x 32 cols

    float acc[4][4][4];
#pragma unroll
    for (int mt = 0; mt < 4; mt++)
#pragma unroll
        for (int nt = 0; nt < 4; nt++)
#pragma unroll
            for (int e = 0; e < 4; e++) acc[mt][nt][e] = 0.f;

    issue(0, 0); issue(1, 1);
    int stc = 0;
#pragma unroll 1
    for (int c = 0; c < NCHUNK; c++) {
        if (c == NCHUNK - 1) { CP_WAIT0(); } else { CP_WAIT1(); }
        __syncthreads();
        if (c + 2 < NCHUNK) {
            int si = stc + 2; if (si >= 3) si -= 3;
            issue(c + 2, si);
        }
        uint32_t stg = sb + (uint32_t)stc * STAGE;
#pragma unroll
        for (int s = 0; s < 4; s++) {
            uint32_t a[4][4], b[4][2];
#pragma unroll
            for (int mt = 0; mt < 4; mt++) {
                int tt = wr * 4 + mt;
                uint32_t ad = stg + (uint32_t)((tt * 4 + s) * 512 + lane * 16);
                asm volatile("ld.shared.v4.b32 {%0,%1,%2,%3}, [%4];"
                    : "=r"(a[mt][0]), "=r"(a[mt][1]), "=r"(a[mt][2]), "=r"(a[mt][3]) : "r"(ad));
            }
#pragma unroll
            for (int nt = 0; nt < 4; nt++) {
                int n8 = wc * 4 + nt;
                uint32_t bd = stg + 16384u + (uint32_t)((n8 * 4 + s) * 256 + lane * 8);
                asm volatile("ld.shared.v2.b32 {%0,%1}, [%2];"
                    : "=r"(b[nt][0]), "=r"(b[nt][1]) : "r"(bd));
            }
#pragma unroll
            for (int mt = 0; mt < 4; mt++)
#pragma unroll
                for (int nt = 0; nt < 4; nt++)
                    mma_tf32(acc[mt][nt], a[mt], b[nt]);
        }
        stc = (stc == 2) ? 0 : stc + 1;
    }

    // ---- fused epilogue (R4-proven: u16 delta tables + on-the-fly mask) ----
    const float invT = 1.0f / TEMP;
    float uR[8], pR[8], uC[8], pC[8];
#pragma unroll
    for (int e = 0; e < 8; e++) { uR[e] = 0.f; pR[e] = 0.f; uC[e] = 0.f; pC[e] = 0.f; }
    int rq = lane >> 2, cq = 2 * (lane & 3);
#pragma unroll
    for (int mt = 0; mt < 4; mt++) {
#pragma unroll
        for (int h = 0; h < 2; h++) {
            int r  = wr * 64 + mt * 16 + rq + h * 8;
            int iB = (i0 + r) & (BSZ - 1);
            float li = slabA[r];
            const unsigned short* dtrow = g_dt  + (size_t)iB * BSZ;
            const unsigned short* dTrow = g_dtT + (size_t)iB * BSZ;
            int ridx = mt * 2 + h;
#pragma unroll
            for (int nt = 0; nt < 4; nt++) {
                int c2  = wc * 32 + nt * 8 + cq;
                int jB2 = (j0 + c2) & (BSZ - 1);
                uint32_t dp  = *(const uint32_t*)(dtrow + jB2);
                uint32_t dTp = *(const uint32_t*)(dTrow + jB2);
#pragma unroll
                for (int e = 0; e < 2; e++) {
                    int cc = c2 + e;
                    float a = acc[mt][nt][h * 2 + e];
                    float x = fmaf(a, invT, -invT);
                    float lj = slabB[cc];
                    float dd = li - lj;
                    float m  = __expf(-0.5f * dd * dd) * RSQRT2PI;
                    float ex = __expf(x);
                    float dv  = (float)((e ? (dp >> 16)  : dp)  & 0xFFFF);
                    float dTv = (float)((e ? (dTp >> 16) : dTp) & 0xFFFF);
                    bool skip = diag && (r == cc);
                    if (!skip) {
                        uR[ridx] = fmaf(ex, dv, uR[ridx]);
                        pR[ridx] = fmaf(m, x, pR[ridx]);
                        if (!diag) {
                            int cidx = nt * 2 + e;
                            uC[cidx] = fmaf(ex, dTv, uC[cidx]);
                            pC[cidx] = fmaf(m, x, pC[cidx]);
                        }
                    }
                }
            }
        }
    }
#pragma unroll
    for (int mt = 0; mt < 4; mt++)
#pragma unroll
        for (int h = 0; h < 2; h++) {
            int r = wr * 64 + mt * 16 + rq + h * 8;
            atomicAdd(&uRow[r], uR[mt * 2 + h]);
            atomicAdd(&pRow[r], pR[mt * 2 + h]);
        }
    if (!diag) {
#pragma unroll
        for (int nt = 0; nt < 4; nt++)
#pragma unroll
            for (int e = 0; e < 2; e++) {
                int cc = wc * 32 + nt * 8 + cq + e;
                atomicAdd(&uCol[cc], uC[nt * 2 + e]);
                atomicAdd(&pCol[cc], pC[nt * 2 + e]);
            }
    }
    __syncthreads();
    if (tid < 128) {
        atomicAdd(&g_u[i0 + tid], uRow[tid]);
        atomicAdd(&g_p[i0 + tid], pRow[tid]);
        if (!diag) {
            atomicAdd(&g_u[j0 + tid], uCol[tid]);
            atomicAdd(&g_p[j0 + tid], pCol[tid]);
        }
    }
}

// ---------------- K4: final reduction -----------------------------------------
__global__ void k_final(float* __restrict__ out) {
    __shared__ float red[512];
    int tid = threadIdx.x;
    float sum = 0.f;
    for (int i = tid; i < NTOT; i += 512) {
        float lp = g_p[i] / g_S[i & (BSZ - 1)] - logf(g_u[i]);
        sum += lp;
    }
    red[tid] = sum; __syncthreads();
    for (int st = 256; st > 0; st >>= 1) { if (tid < st) red[tid] += red[tid + st]; __syncthreads(); }
    if (tid == 0) out[0] = -red[0] / (float)NTOT;
}

// ---------------- entry --------------------------------------------------------
extern "C" void kernel_launch(void* const* d_in, const int* in_sizes, int n_in,
                              void* d_out, int out_size) {
    (void)in_sizes; (void)n_in; (void)out_size;
    const float* feats  = (const float*)d_in[0];
    const float* labels = (const float*)d_in[1];
    float* out = (float*)d_out;

    cudaFuncSetAttribute(k_main, cudaFuncAttributeMaxDynamicSharedMemorySize, DSMEM);

    k_prep  <<<6144, 256>>>(feats);
    k_sort  <<<1, 1024>>>(labels);
    k_tab   <<<2048, 256>>>(labels);
    k_transp<<<1024, 256>>>();
    k_main  <<<528, 256, DSMEM>>>(labels);
    k_final <<<1, 512>>>(out);
}

// round 8
// speedup vs baseline: 1.3703x; 1.1456x over previous
#include <cuda_runtime.h>
#include <cuda_fp16.h>
#include <cstdint>
#include <math.h>

// ---------------- problem constants ----------------
constexpr int BSZ   = 2048;
constexpr int VIEWS = 2;
constexpr int DIM   = 512;
constexpr int NTOT  = BSZ * VIEWS;          // 4096
constexpr float TEMP = 0.07f;
constexpr float RSQRT2PI = 0.3989422804014327f;

// GEMM tiling: 128x128 CTA tile, 8 warps of 64x32, fp16 m16n8k16, K-chunks of 32
constexpr int KC = 32;
constexpr int NCHUNK = DIM / KC;             // 16
constexpr int STAGE = 16384;                 // A 8K + B 8K per chunk
constexpr int NSTG = 3;
constexpr int DSMEM = NSTG * STAGE;          // 49152 B -> 2 CTAs/SM easily

// ---------------- device scratch --------------------
// fragment-major fp16 operand images (written by k_prep, consumed raw by cp.async)
// A: [rowGroup 0..31][chunk 0..15][m16tile 0..7][slice 0..1][lane 0..31][uint4]
__device__ __align__(16) unsigned g_FA[8192 * 32 * 4];    // 4 MB
// B: [colGroup 0..31][chunk 0..15][n8tile 0..15][slice 0..1][lane 0..31][uint2]
__device__ __align__(16) unsigned g_FB[16384 * 32 * 2];   // 4 MB
__device__ __align__(16) unsigned short g_dt [(size_t)BSZ * BSZ];   // delta[i][j], 8 MB
__device__ __align__(16) unsigned short g_dtT[(size_t)BSZ * BSZ];   // delta[j][i], 8 MB
__device__ float g_S[BSZ];
__device__ float g_sorted[BSZ];
__device__ float g_u[NTOT];
__device__ float g_p[NTOT];

// ---------------- PTX helpers -----------------------
__device__ __forceinline__ uint32_t smem_u32(const void* p) {
    uint32_t a;
    asm("{ .reg .u64 t; cvta.to.shared.u64 t, %1; cvt.u32.u64 %0, t; }" : "=r"(a) : "l"(p));
    return a;
}
__device__ __forceinline__ void cpa16(uint32_t d, const void* s) {
    asm volatile("cp.async.cg.shared.global [%0], [%1], 16;" :: "r"(d), "l"(s) : "memory");
}
#define CP_COMMIT() asm volatile("cp.async.commit_group;" ::: "memory")
#define CP_WAIT0()  asm volatile("cp.async.wait_group 0;" ::: "memory")
#define CP_WAIT1()  asm volatile("cp.async.wait_group 1;" ::: "memory")
__device__ __forceinline__ void mma_f16(float* c, const uint32_t* a, const uint32_t* b) {
    asm volatile("mma.sync.aligned.m16n8k16.row.col.f32.f16.f16.f32 "
        "{%0,%1,%2,%3}, {%4,%5,%6,%7}, {%8,%9}, {%0,%1,%2,%3};"
        : "+f"(c[0]), "+f"(c[1]), "+f"(c[2]), "+f"(c[3])
        : "r"(a[0]), "r"(a[1]), "r"(a[2]), "r"(a[3]), "r"(b[0]), "r"(b[1]));
}

// ---------------- K0: fp16 convert + fragment-major scatter + zero accums ----
__device__ __forceinline__ float ld_feat(const float* feats, int row, int col) {
    int b = row & (BSZ - 1), v = row >> 11;
    return feats[(size_t)((b << 1) | v) * DIM + col];
}
__device__ __forceinline__ unsigned pack2(const float* feats, int row, int col) {
    __half2 h = __floats2half2_rn(ld_feat(feats, row, col), ld_feat(feats, row, col + 1));
    return *(unsigned*)&h;
}
__global__ void k_prep(const float* __restrict__ feats) {
    int tid = blockIdx.x * blockDim.x + threadIdx.x;   // 3072*256 = 786432
    if (tid < NTOT) { g_u[tid] = 0.f; g_p[tid] = 0.f; }
    int gw = tid >> 5;           // warp id 0..24575
    int l  = tid & 31;
    int g  = l >> 2, tg = l & 3;
    if (gw < 8192) {
        // A warp: gw = rg*256 + ch*16 + t*2 + s
        int s = gw & 1, t = (gw >> 1) & 7, ch = (gw >> 4) & 15, rg = gw >> 8;
        int R = rg * 128 + t * 16 + g;
        int C = ch * 32 + s * 16 + tg * 2;
        uint4 o;
        o.x = pack2(feats, R,     C);
        o.y = pack2(feats, R + 8, C);
        o.z = pack2(feats, R,     C + 8);
        o.w = pack2(feats, R + 8, C + 8);
        ((uint4*)g_FA)[(size_t)gw * 32 + l] = o;
    } else {
        // B warp: w2 = ng*512 + ch*32 + n8*2 + s
        int w2 = gw - 8192;
        int s = w2 & 1, n8 = (w2 >> 1) & 15, ch = (w2 >> 5) & 15, ng = w2 >> 9;
        int J = ng * 128 + n8 * 8 + g;
        int K = ch * 32 + s * 16 + tg * 2;
        uint2 o;
        o.x = pack2(feats, J, K);
        o.y = pack2(feats, J, K + 8);
        ((uint2*)g_FB)[(size_t)w2 * 32 + l] = o;
    }
}

// ---------------- K1: bitonic sort of labels ---------------------------------
__global__ void k_sort(const float* __restrict__ labels) {
    __shared__ float s[BSZ];
    int tid = threadIdx.x;
    s[tid] = labels[tid]; s[tid + 1024] = labels[tid + 1024];
    __syncthreads();
    for (int k = 2; k <= BSZ; k <<= 1)
        for (int j = k >> 1; j > 0; j >>= 1) {
            for (int i = tid; i < BSZ; i += 1024) {
                int ixj = i ^ j;
                if (ixj > i) {
                    bool up = ((i & k) == 0);
                    float a = s[i], bb = s[ixj];
                    if ((a > bb) == up) { s[i] = bb; s[ixj] = a; }
                }
            }
            __syncthreads();
        }
    g_sorted[tid] = s[tid]; g_sorted[tid + 1024] = s[tid + 1024];
}

// ---------------- K2: delta^T table (uint16) + S row sums --------------------
__global__ void k_tab(const float* __restrict__ labels) {
    __shared__ float s[BSZ];
    __shared__ float red[256];
    int tid = threadIdx.x;
    int jb  = blockIdx.x;
    for (int m = tid; m < BSZ; m += 256) s[m] = g_sorted[m];
    __syncthreads();
    float c = labels[jb];
    int lo = 0, hi = BSZ;
    while (lo < hi) { int mid = (lo + hi) >> 1; if (s[mid] < c) lo = mid + 1; else hi = mid; }
    int iC = lo;
    float rs = 0.f;
    for (int ib = tid; ib < BSZ; ib += 256) {
        float li = labels[ib];
        float dl = c - li;
        float t2 = dl * dl;
        rs += expf(-0.5f * t2) * RSQRT2PI;
        int l0 = 0, l1 = iC;
        int r0 = iC, r1 = BSZ - 1;
#pragma unroll 1
        while (l0 < l1 || r0 < r1) {
            if (l0 < l1) { int mid = (l0 + l1) >> 1; float d = c - s[mid];
                           if (d * d <= t2) l1 = mid; else l0 = mid + 1; }
            if (r0 < r1) { int mid = (r0 + r1 + 1) >> 1; float d = s[mid] - c;
                           if (d * d <= t2) r0 = mid; else r1 = mid - 1; }
        }
        int cnt = r0 - l0 + 1;
        g_dtT[(size_t)jb * BSZ + ib] = (unsigned short)(VIEWS * (BSZ - cnt));
    }
    red[tid] = rs; __syncthreads();
    for (int st = 128; st > 0; st >>= 1) { if (tid < st) red[tid] += red[tid + st]; __syncthreads(); }
    if (tid == 0) g_S[jb] = (float)VIEWS * red[0] - RSQRT2PI;
}

// ---------------- K2b: transpose delta^T -> delta (ushort, proven R4) --------
__global__ void k_transp() {
    __shared__ unsigned short tile[64][72];
    int bx = blockIdx.x & 31, by = blockIdx.x >> 5;
    int r  = threadIdx.x >> 2;
    int c0 = (threadIdx.x & 3) * 16;
    const unsigned short* src = g_dtT + (size_t)(by * 64 + r) * BSZ + bx * 64 + c0;
    *(uint4*)&tile[r][c0]     = *(const uint4*)src;
    *(uint4*)&tile[r][c0 + 8] = *(const uint4*)(src + 8);
    __syncthreads();
    unsigned short ov[16];
#pragma unroll
    for (int k = 0; k < 16; k++) ov[k] = tile[c0 + k][r];
    unsigned short* dst = g_dt + (size_t)(bx * 64 + r) * BSZ + by * 64 + c0;
    *(uint4*)dst       = *(const uint4*)ov;
    *(uint4*)(dst + 8) = *(const uint4*)(ov + 8);
}

// ---------------- K3: fp16 mma.sync GEMM + fused epilogue --------------------
__global__ __launch_bounds__(256, 2) void k_main(const float* __restrict__ labels) {
    extern __shared__ __align__(16) char smem[];
    __shared__ float uRow[128], pRow[128], uCol[128], pCol[128];
    __shared__ float slabA[128], slabB[128];
    uint32_t sb = smem_u32(smem);
    int tid = threadIdx.x, wid = tid >> 5, lane = tid & 31;

    // triangular tile index
    int t  = blockIdx.x;
    int bi = (int)((sqrtf(8.f * (float)t + 1.f) - 1.f) * 0.5f);
    while ((bi + 1) * (bi + 2) / 2 <= t) bi++;
    while (bi * (bi + 1) / 2 > t) bi--;
    int bj = t - bi * (bi + 1) / 2;
    int i0 = bi * 128, j0 = bj * 128;
    bool diag = (bi == bj);

    if (tid < 128) {
        uRow[tid] = 0.f; pRow[tid] = 0.f; uCol[tid] = 0.f; pCol[tid] = 0.f;
        slabA[tid] = labels[(i0 + tid) & (BSZ - 1)];
        slabB[tid] = labels[(j0 + tid) & (BSZ - 1)];
    }

    // 128KB per 128-row/col group for both images
    const char* Ab = (const char*)g_FA + (size_t)(i0 >> 7) * 131072;
    const char* Bb = (const char*)g_FB + (size_t)(j0 >> 7) * 131072;

    auto issue = [&](int c, int si) {
        uint32_t stg = sb + (uint32_t)si * STAGE;
        const char* As = Ab + (size_t)c * 8192;
        const char* Bs = Bb + (size_t)c * 8192;
        cpa16(stg + tid * 16,                 As + tid * 16);
        cpa16(stg + 4096 + tid * 16,          As + 4096 + tid * 16);
        cpa16(stg + 8192 + tid * 16,          Bs + tid * 16);
        cpa16(stg + 12288 + tid * 16,         Bs + 4096 + tid * 16);
        CP_COMMIT();
    };

    int wr = wid & 1, wc = wid >> 1;   // warp tile 64 rows x 32 cols

    float acc[4][4][4];
#pragma unroll
    for (int mt = 0; mt < 4; mt++)
#pragma unroll
        for (int nt = 0; nt < 4; nt++)
#pragma unroll
            for (int e = 0; e < 4; e++) acc[mt][nt][e] = 0.f;

    issue(0, 0); issue(1, 1);
    int stc = 0;
#pragma unroll 1
    for (int c = 0; c < NCHUNK; c++) {
        if (c == NCHUNK - 1) { CP_WAIT0(); } else { CP_WAIT1(); }
        __syncthreads();
        if (c + 2 < NCHUNK) {
            int si = stc + 2; if (si >= 3) si -= 3;
            issue(c + 2, si);
        }
        uint32_t stg = sb + (uint32_t)stc * STAGE;
#pragma unroll
        for (int s = 0; s < 2; s++) {
            uint32_t a[4][4], b[4][2];
#pragma unroll
            for (int mt = 0; mt < 4; mt++) {
                int tt = wr * 4 + mt;
                uint32_t ad = stg + (uint32_t)((tt * 2 + s) * 512 + lane * 16);
                asm volatile("ld.shared.v4.b32 {%0,%1,%2,%3}, [%4];"
                    : "=r"(a[mt][0]), "=r"(a[mt][1]), "=r"(a[mt][2]), "=r"(a[mt][3]) : "r"(ad));
            }
#pragma unroll
            for (int nt = 0; nt < 4; nt++) {
                int n8 = wc * 4 + nt;
                uint32_t bd = stg + 8192u + (uint32_t)((n8 * 2 + s) * 256 + lane * 8);
                asm volatile("ld.shared.v2.b32 {%0,%1}, [%2];"
                    : "=r"(b[nt][0]), "=r"(b[nt][1]) : "r"(bd));
            }
#pragma unroll
            for (int mt = 0; mt < 4; mt++)
#pragma unroll
                for (int nt = 0; nt < 4; nt++)
                    mma_f16(acc[mt][nt], a[mt], b[nt]);
        }
        stc = (stc == 2) ? 0 : stc + 1;
    }

    // ---- fused epilogue (u16 delta tables + on-the-fly mask) ----
    const float invT = 1.0f / TEMP;
    float uR[8], pR[8], uC[8], pC[8];
#pragma unroll
    for (int e = 0; e < 8; e++) { uR[e] = 0.f; pR[e] = 0.f; uC[e] = 0.f; pC[e] = 0.f; }
    int rq = lane >> 2, cq = 2 * (lane & 3);
#pragma unroll
    for (int mt = 0; mt < 4; mt++) {
#pragma unroll
        for (int h = 0; h < 2; h++) {
            int r  = wr * 64 + mt * 16 + rq + h * 8;
            int iB = (i0 + r) & (BSZ - 1);
            float li = slabA[r];
            const unsigned short* dtrow = g_dt  + (size_t)iB * BSZ;
            const unsigned short* dTrow = g_dtT + (size_t)iB * BSZ;
            int ridx = mt * 2 + h;
#pragma unroll
            for (int nt = 0; nt < 4; nt++) {
                int c2  = wc * 32 + nt * 8 + cq;
                int jB2 = (j0 + c2) & (BSZ - 1);
                uint32_t dp  = *(const uint32_t*)(dtrow + jB2);
                uint32_t dTp = *(const uint32_t*)(dTrow + jB2);
#pragma unroll
                for (int e = 0; e < 2; e++) {
                    int cc = c2 + e;
                    float a = acc[mt][nt][h * 2 + e];
                    float x = fmaf(a, invT, -invT);
                    float lj = slabB[cc];
                    float dd = li - lj;
                    float m  = __expf(-0.5f * dd * dd) * RSQRT2PI;
                    float ex = __expf(x);
                    float dv  = (float)((e ? (dp >> 16)  : dp)  & 0xFFFF);
                    float dTv = (float)((e ? (dTp >> 16) : dTp) & 0xFFFF);
                    bool skip = diag && (r == cc);
                    if (!skip) {
                        uR[ridx] = fmaf(ex, dv, uR[ridx]);
                        pR[ridx] = fmaf(m, x, pR[ridx]);
                        if (!diag) {
                            int cidx = nt * 2 + e;
                            uC[cidx] = fmaf(ex, dTv, uC[cidx]);
                            pC[cidx] = fmaf(m, x, pC[cidx]);
                        }
                    }
                }
            }
        }
    }
#pragma unroll
    for (int mt = 0; mt < 4; mt++)
#pragma unroll
        for (int h = 0; h < 2; h++) {
            int r = wr * 64 + mt * 16 + rq + h * 8;
            atomicAdd(&uRow[r], uR[mt * 2 + h]);
            atomicAdd(&pRow[r], pR[mt * 2 + h]);
        }
    if (!diag) {
#pragma unroll
        for (int nt = 0; nt < 4; nt++)
#pragma unroll
            for (int e = 0; e < 2; e++) {
                int cc = wc * 32 + nt * 8 + cq + e;
                atomicAdd(&uCol[cc], uC[nt * 2 + e]);
                atomicAdd(&pCol[cc], pC[nt * 2 + e]);
            }
    }
    __syncthreads();
    if (tid < 128) {
        atomicAdd(&g_u[i0 + tid], uRow[tid]);
        atomicAdd(&g_p[i0 + tid], pRow[tid]);
        if (!diag) {
            atomicAdd(&g_u[j0 + tid], uCol[tid]);
            atomicAdd(&g_p[j0 + tid], pCol[tid]);
        }
    }
}

// ---------------- K4: final reduction -----------------------------------------
__global__ void k_final(float* __restrict__ out) {
    __shared__ float red[512];
    int tid = threadIdx.x;
    float sum = 0.f;
    for (int i = tid; i < NTOT; i += 512) {
        float lp = g_p[i] / g_S[i & (BSZ - 1)] - logf(g_u[i]);
        sum += lp;
    }
    red[tid] = sum; __syncthreads();
    for (int st = 256; st > 0; st >>= 1) { if (tid < st) red[tid] += red[tid + st]; __syncthreads(); }
    if (tid == 0) out[0] = -red[0] / (float)NTOT;
}

// ---------------- entry --------------------------------------------------------
extern "C" void kernel_launch(void* const* d_in, const int* in_sizes, int n_in,
                              void* d_out, int out_size) {
    (void)in_sizes; (void)n_in; (void)out_size;
    const float* feats  = (const float*)d_in[0];
    const float* labels = (const float*)d_in[1];
    float* out = (float*)d_out;

    cudaFuncSetAttribute(k_main, cudaFuncAttributeMaxDynamicSharedMemorySize, DSMEM);

    k_prep  <<<3072, 256>>>(feats);
    k_sort  <<<1, 1024>>>(labels);
    k_tab   <<<2048, 256>>>(labels);
    k_transp<<<1024, 256>>>();
    k_main  <<<528, 256, DSMEM>>>(labels);
    k_final <<<1, 512>>>(out);
}

// round 9
// speedup vs baseline: 1.4140x; 1.0319x over previous
#include <cuda_runtime.h>
#include <cuda_fp16.h>
#include <cstdint>
#include <math.h>

// ---------------- problem constants ----------------
constexpr int BSZ   = 2048;
constexpr int VIEWS = 2;
constexpr int DIM   = 512;
constexpr int NTOT  = BSZ * VIEWS;          // 4096
constexpr float TEMP = 0.07f;
constexpr float RSQRT2PI = 0.3989422804014327f;

// GEMM tiling: 128x128 CTA tile, 8 warps of 64x32, fp16 m16n8k16, K-chunks of 32
constexpr int KC = 32;
constexpr int NCHUNK = DIM / KC;             // 16
constexpr int STAGE = 16384;                 // A 8K + B 8K per chunk
constexpr int NSTG = 4;
constexpr int DSMEM = NSTG * STAGE;          // 65536 B -> 2 CTAs/SM

// ---------------- device scratch --------------------
// fragment-major fp16 operand images (written by k_prep, consumed raw by cp.async)
__device__ __align__(16) unsigned g_FA[8192 * 32 * 4];    // 4 MB
__device__ __align__(16) unsigned g_FB[16384 * 32 * 2];   // 4 MB
__device__ __align__(16) unsigned short g_dt [(size_t)BSZ * BSZ];   // delta[i][j], 8 MB
__device__ __align__(16) unsigned short g_dtT[(size_t)BSZ * BSZ];   // delta[j][i], 8 MB
__device__ unsigned g_pos[BSZ];              // (lower_bound(li) << 16) | last_index(<= li)
__device__ float g_S[BSZ];
__device__ float g_sorted[BSZ];
__device__ float g_u[NTOT];
__device__ float g_p[NTOT];

// ---------------- PTX helpers -----------------------
__device__ __forceinline__ uint32_t smem_u32(const void* p) {
    uint32_t a;
    asm("{ .reg .u64 t; cvta.to.shared.u64 t, %1; cvt.u32.u64 %0, t; }" : "=r"(a) : "l"(p));
    return a;
}
__device__ __forceinline__ void cpa16(uint32_t d, const void* s) {
    asm volatile("cp.async.cg.shared.global [%0], [%1], 16;" :: "r"(d), "l"(s) : "memory");
}
#define CP_COMMIT() asm volatile("cp.async.commit_group;" ::: "memory")
#define CP_WAIT0()  asm volatile("cp.async.wait_group 0;" ::: "memory")
#define CP_WAIT1()  asm volatile("cp.async.wait_group 1;" ::: "memory")
#define CP_WAIT2()  asm volatile("cp.async.wait_group 2;" ::: "memory")
__device__ __forceinline__ void mma_f16(float* c, const uint32_t* a, const uint32_t* b) {
    asm volatile("mma.sync.aligned.m16n8k16.row.col.f32.f16.f16.f32 "
        "{%0,%1,%2,%3}, {%4,%5,%6,%7}, {%8,%9}, {%0,%1,%2,%3};"
        : "+f"(c[0]), "+f"(c[1]), "+f"(c[2]), "+f"(c[3])
        : "r"(a[0]), "r"(a[1]), "r"(a[2]), "r"(a[3]), "r"(b[0]), "r"(b[1]));
}

// ---------------- K0: fp16 convert + fragment-major scatter + zero accums ----
__device__ __forceinline__ float ld_feat(const float* feats, int row, int col) {
    int b = row & (BSZ - 1), v = row >> 11;
    return feats[(size_t)((b << 1) | v) * DIM + col];
}
__device__ __forceinline__ unsigned pack2(const float* feats, int row, int col) {
    __half2 h = __floats2half2_rn(ld_feat(feats, row, col), ld_feat(feats, row, col + 1));
    return *(unsigned*)&h;
}
__global__ void k_prep(const float* __restrict__ feats) {
    int tid = blockIdx.x * blockDim.x + threadIdx.x;   // 3072*256 = 786432
    if (tid < NTOT) { g_u[tid] = 0.f; g_p[tid] = 0.f; }
    int gw = tid >> 5;           // warp id 0..24575
    int l  = tid & 31;
    int g  = l >> 2, tg = l & 3;
    if (gw < 8192) {
        int s = gw & 1, t = (gw >> 1) & 7, ch = (gw >> 4) & 15, rg = gw >> 8;
        int R = rg * 128 + t * 16 + g;
        int C = ch * 32 + s * 16 + tg * 2;
        uint4 o;
        o.x = pack2(feats, R,     C);
        o.y = pack2(feats, R + 8, C);
        o.z = pack2(feats, R,     C + 8);
        o.w = pack2(feats, R + 8, C + 8);
        ((uint4*)g_FA)[(size_t)gw * 32 + l] = o;
    } else {
        int w2 = gw - 8192;
        int s = w2 & 1, n8 = (w2 >> 1) & 15, ch = (w2 >> 5) & 15, ng = w2 >> 9;
        int J = ng * 128 + n8 * 8 + g;
        int K = ch * 32 + s * 16 + tg * 2;
        uint2 o;
        o.x = pack2(feats, J, K);
        o.y = pack2(feats, J, K + 8);
        ((uint2*)g_FB)[(size_t)w2 * 32 + l] = o;
    }
}

// ---------------- K1: bitonic sort of labels + per-label positions ----------
__global__ void k_sort(const float* __restrict__ labels) {
    __shared__ float s[BSZ];
    int tid = threadIdx.x;
    s[tid] = labels[tid]; s[tid + 1024] = labels[tid + 1024];
    __syncthreads();
    for (int k = 2; k <= BSZ; k <<= 1)
        for (int j = k >> 1; j > 0; j >>= 1) {
            for (int i = tid; i < BSZ; i += 1024) {
                int ixj = i ^ j;
                if (ixj > i) {
                    bool up = ((i & k) == 0);
                    float a = s[i], bb = s[ixj];
                    if ((a > bb) == up) { s[i] = bb; s[ixj] = a; }
                }
            }
            __syncthreads();
        }
    g_sorted[tid] = s[tid]; g_sorted[tid + 1024] = s[tid + 1024];
    // per-label sorted positions: p = first index >= li, q-1 = last index <= li
    for (int ib = tid; ib < BSZ; ib += 1024) {
        float li = labels[ib];
        int p = 0, q = 0;
#pragma unroll
        for (int st = 2048; st; st >>= 1) {
            int np = p + st, nq = q + st;
            if (np <= BSZ && s[np - 1] <  li) p = np;
            if (nq <= BSZ && s[nq - 1] <= li) q = nq;
        }
        g_pos[ib] = ((unsigned)p << 16) | (unsigned)(q - 1);
    }
}

// ---------------- K2: delta^T table (uint16) + S row sums --------------------
// One mirrored-boundary search per target; the near boundary comes from g_pos.
__global__ void k_tab(const float* __restrict__ labels) {
    __shared__ float s[BSZ];
    __shared__ float red[256];
    int tid = threadIdx.x;
    int jb  = blockIdx.x;
    for (int m = tid; m < BSZ; m += 256) s[m] = g_sorted[m];
    __syncthreads();
    float c = labels[jb];
    float rs = 0.f;
    unsigned short* orow = g_dtT + (size_t)jb * BSZ;
#pragma unroll 1
    for (int it = 0; it < 4; it++) {
        int ib0 = tid + it * 512;
        int ib1 = ib0 + 256;
        float li0 = labels[ib0], li1 = labels[ib1];
        float d0 = c - li0, d1 = c - li1;
        rs += expf(-0.5f * d0 * d0) + expf(-0.5f * d1 * d1);
        float mir0 = c + d0, mir1 = c + d1;
        bool le0 = d0 > 0.f, le1 = d1 > 0.f;   // true: count(<= mir) -> right bound
        int q0 = 0, q1 = 0;
#pragma unroll
        for (int st = 2048; st; st >>= 1) {
            int n0 = q0 + st, n1 = q1 + st;
            if (n0 <= BSZ) { float v = s[n0 - 1]; if (le0 ? (v <= mir0) : (v < mir0)) q0 = n0; }
            if (n1 <= BSZ) { float v = s[n1 - 1]; if (le1 ? (v <= mir1) : (v < mir1)) q1 = n1; }
        }
        unsigned pos0 = g_pos[ib0], pos1 = g_pos[ib1];
        int L0 = le0 ? (int)(pos0 >> 16) : q0;
        int R0 = le0 ? (q0 - 1)          : (int)(pos0 & 0xFFFFu);
        int L1 = le1 ? (int)(pos1 >> 16) : q1;
        int R1 = le1 ? (q1 - 1)          : (int)(pos1 & 0xFFFFu);
        orow[ib0] = (unsigned short)(VIEWS * (BSZ - (R0 - L0 + 1)));
        orow[ib1] = (unsigned short)(VIEWS * (BSZ - (R1 - L1 + 1)));
    }
    red[tid] = rs; __syncthreads();
    for (int st = 128; st > 0; st >>= 1) { if (tid < st) red[tid] += red[tid + st]; __syncthreads(); }
    if (tid == 0) g_S[jb] = ((float)VIEWS * red[0] - 1.0f) * RSQRT2PI;
}

// ---------------- K2b: transpose delta^T -> delta (ushort) -------------------
__global__ void k_transp() {
    __shared__ unsigned short tile[64][72];
    int bx = blockIdx.x & 31, by = blockIdx.x >> 5;
    int r  = threadIdx.x >> 2;
    int c0 = (threadIdx.x & 3) * 16;
    const unsigned short* src = g_dtT + (size_t)(by * 64 + r) * BSZ + bx * 64 + c0;
    *(uint4*)&tile[r][c0]     = *(const uint4*)src;
    *(uint4*)&tile[r][c0 + 8] = *(const uint4*)(src + 8);
    __syncthreads();
    unsigned short ov[16];
#pragma unroll
    for (int k = 0; k < 16; k++) ov[k] = tile[c0 + k][r];
    unsigned short* dst = g_dt + (size_t)(bx * 64 + r) * BSZ + by * 64 + c0;
    *(uint4*)dst       = *(const uint4*)ov;
    *(uint4*)(dst + 8) = *(const uint4*)(ov + 8);
}

// ---------------- K3: fp16 mma.sync GEMM + fused epilogue --------------------
__global__ __launch_bounds__(256, 2) void k_main(const float* __restrict__ labels) {
    extern __shared__ __align__(16) char smem[];
    __shared__ float uRow[128], pRow[128], uCol[128], pCol[128];
    __shared__ float slabA[128], slabB[128];
    uint32_t sb = smem_u32(smem);
    int tid = threadIdx.x, wid = tid >> 5, lane = tid & 31;

    // triangular tile index
    int t  = blockIdx.x;
    int bi = (int)((sqrtf(8.f * (float)t + 1.f) - 1.f) * 0.5f);
    while ((bi + 1) * (bi + 2) / 2 <= t) bi++;
    while (bi * (bi + 1) / 2 > t) bi--;
    int bj = t - bi * (bi + 1) / 2;
    int i0 = bi * 128, j0 = bj * 128;
    bool diag = (bi == bj);

    if (tid < 128) {
        uRow[tid] = 0.f; pRow[tid] = 0.f; uCol[tid] = 0.f; pCol[tid] = 0.f;
        slabA[tid] = labels[(i0 + tid) & (BSZ - 1)];
        slabB[tid] = labels[(j0 + tid) & (BSZ - 1)];
    }

    const char* Ab = (const char*)g_FA + (size_t)(i0 >> 7) * 131072;
    const char* Bb = (const char*)g_FB + (size_t)(j0 >> 7) * 131072;

    auto issue = [&](int c, int si) {
        uint32_t stg = sb + (uint32_t)si * STAGE;
        const char* As = Ab + (size_t)c * 8192;
        const char* Bs = Bb + (size_t)c * 8192;
        cpa16(stg + tid * 16,          As + tid * 16);
        cpa16(stg + 4096 + tid * 16,   As + 4096 + tid * 16);
        cpa16(stg + 8192 + tid * 16,   Bs + tid * 16);
        cpa16(stg + 12288 + tid * 16,  Bs + 4096 + tid * 16);
        CP_COMMIT();
    };

    int wr = wid & 1, wc = wid >> 1;   // warp tile 64 rows x 32 cols

    float acc[4][4][4];
#pragma unroll
    for (int mt = 0; mt < 4; mt++)
#pragma unroll
        for (int nt = 0; nt < 4; nt++)
#pragma unroll
            for (int e = 0; e < 4; e++) acc[mt][nt][e] = 0.f;

    issue(0, 0); issue(1, 1); issue(2, 2);
    int stc = 0;
#pragma unroll 1
    for (int c = 0; c < NCHUNK; c++) {
        if (c < NCHUNK - 3)      { CP_WAIT2(); }
        else if (c == NCHUNK - 3){ CP_WAIT2(); }
        else if (c == NCHUNK - 2){ CP_WAIT1(); }
        else                     { CP_WAIT0(); }
        __syncthreads();
        if (c + 3 < NCHUNK) {
            int si = stc + 3; if (si >= NSTG) si -= NSTG;
            issue(c + 3, si);
        }
        uint32_t stg = sb + (uint32_t)stc * STAGE;
#pragma unroll
        for (int s = 0; s < 2; s++) {
            uint32_t a[4][4], b[4][2];
#pragma unroll
            for (int mt = 0; mt < 4; mt++) {
                int tt = wr * 4 + mt;
                uint32_t ad = stg + (uint32_t)((tt * 2 + s) * 512 + lane * 16);
                asm volatile("ld.shared.v4.b32 {%0,%1,%2,%3}, [%4];"
                    : "=r"(a[mt][0]), "=r"(a[mt][1]), "=r"(a[mt][2]), "=r"(a[mt][3]) : "r"(ad));
            }
#pragma unroll
            for (int nt = 0; nt < 4; nt++) {
                int n8 = wc * 4 + nt;
                uint32_t bd = stg + 8192u + (uint32_t)((n8 * 2 + s) * 256 + lane * 8);
                asm volatile("ld.shared.v2.b32 {%0,%1}, [%2];"
                    : "=r"(b[nt][0]), "=r"(b[nt][1]) : "r"(bd));
            }
#pragma unroll
            for (int mt = 0; mt < 4; mt++)
#pragma unroll
                for (int nt = 0; nt < 4; nt++)
                    mma_f16(acc[mt][nt], a[mt], b[nt]);
        }
        stc = (stc == NSTG - 1) ? 0 : stc + 1;
    }

    // ---- fused epilogue (u16 delta tables + on-the-fly mask) ----
    const float invT = 1.0f / TEMP;
    float uR[8], pR[8], uC[8], pC[8];
#pragma unroll
    for (int e = 0; e < 8; e++) { uR[e] = 0.f; pR[e] = 0.f; uC[e] = 0.f; pC[e] = 0.f; }
    int rq = lane >> 2, cq = 2 * (lane & 3);
#pragma unroll
    for (int mt = 0; mt < 4; mt++) {
#pragma unroll
        for (int h = 0; h < 2; h++) {
            int r  = wr * 64 + mt * 16 + rq + h * 8;
            int iB = (i0 + r) & (BSZ - 1);
            float li = slabA[r];
            const unsigned short* dtrow = g_dt  + (size_t)iB * BSZ;
            const unsigned short* dTrow = g_dtT + (size_t)iB * BSZ;
            int ridx = mt * 2 + h;
#pragma unroll
            for (int nt = 0; nt < 4; nt++) {
                int c2  = wc * 32 + nt * 8 + cq;
                int jB2 = (j0 + c2) & (BSZ - 1);
                uint32_t dp  = *(const uint32_t*)(dtrow + jB2);
                uint32_t dTp = *(const uint32_t*)(dTrow + jB2);
#pragma unroll
                for (int e = 0; e < 2; e++) {
                    int cc = c2 + e;
                    float a = acc[mt][nt][h * 2 + e];
                    float x = fmaf(a, invT, -invT);
                    float lj = slabB[cc];
                    float dd = li - lj;
                    float m  = __expf(-0.5f * dd * dd) * RSQRT2PI;
                    float ex = __expf(x);
                    float dv  = (float)((e ? (dp >> 16)  : dp)  & 0xFFFF);
                    float dTv = (float)((e ? (dTp >> 16) : dTp) & 0xFFFF);
                    bool skip = diag && (r == cc);
                    if (!skip) {
                        uR[ridx] = fmaf(ex, dv, uR[ridx]);
                        pR[ridx] = fmaf(m, x, pR[ridx]);
                        if (!diag) {
                            int cidx = nt * 2 + e;
                            uC[cidx] = fmaf(ex, dTv, uC[cidx]);
                            pC[cidx] = fmaf(m, x, pC[cidx]);
                        }
                    }
                }
            }
        }
    }
#pragma unroll
    for (int mt = 0; mt < 4; mt++)
#pragma unroll
        for (int h = 0; h < 2; h++) {
            int r = wr * 64 + mt * 16 + rq + h * 8;
            atomicAdd(&uRow[r], uR[mt * 2 + h]);
            atomicAdd(&pRow[r], pR[mt * 2 + h]);
        }
    if (!diag) {
#pragma unroll
        for (int nt = 0; nt < 4; nt++)
#pragma unroll
            for (int e = 0; e < 2; e++) {
                int cc = wc * 32 + nt * 8 + cq + e;
                atomicAdd(&uCol[cc], uC[nt * 2 + e]);
                atomicAdd(&pCol[cc], pC[nt * 2 + e]);
            }
    }
    __syncthreads();
    if (tid < 128) {
        atomicAdd(&g_u[i0 + tid], uRow[tid]);
        atomicAdd(&g_p[i0 + tid], pRow[tid]);
        if (!diag) {
            atomicAdd(&g_u[j0 + tid], uCol[tid]);
            atomicAdd(&g_p[j0 + tid], pCol[tid]);
        }
    }
}

// ---------------- K4: final reduction -----------------------------------------
__global__ void k_final(float* __restrict__ out) {
    __shared__ float red[512];
    int tid = threadIdx.x;
    float sum = 0.f;
    for (int i = tid; i < NTOT; i += 512) {
        float lp = g_p[i] / g_S[i & (BSZ - 1)] - logf(g_u[i]);
        sum += lp;
    }
    red[tid] = sum; __syncthreads();
    for (int st = 256; st > 0; st >>= 1) { if (tid < st) red[tid] += red[tid + st]; __syncthreads(); }
    if (tid == 0) out[0] = -red[0] / (float)NTOT;
}

// ---------------- entry --------------------------------------------------------
extern "C" void kernel_launch(void* const* d_in, const int* in_sizes, int n_in,
                              void* d_out, int out_size) {
    (void)in_sizes; (void)n_in; (void)out_size;
    const float* feats  = (const float*)d_in[0];
    const float* labels = (const float*)d_in[1];
    float* out = (float*)d_out;

    cudaFuncSetAttribute(k_main, cudaFuncAttributeMaxDynamicSharedMemorySize, DSMEM);

    k_prep  <<<3072, 256>>>(feats);
    k_sort  <<<1, 1024>>>(labels);
    k_tab   <<<2048, 256>>>(labels);
    k_transp<<<1024, 256>>>();
    k_main  <<<528, 256, DSMEM>>>(labels);
    k_final <<<1, 512>>>(out);
}

// round 10
// speedup vs baseline: 1.5899x; 1.1244x over previous
#include <cuda_runtime.h>
#include <cuda_fp16.h>
#include <cstdint>
#include <math.h>

// ---------------- problem constants ----------------
constexpr int BSZ   = 2048;
constexpr int VIEWS = 2;
constexpr int DIM   = 512;
constexpr int NTOT  = BSZ * VIEWS;          // 4096
constexpr float TEMP = 0.07f;
constexpr float RSQRT2PI = 0.3989422804014327f;

// GEMM tiling: 128x128 CTA tile, 8 warps of 64x32, fp16 m16n8k16, K-chunks of 32
constexpr int KC = 32;
constexpr int NCHUNK = DIM / KC;             // 16
constexpr int STAGE = 16384;                 // A 8K + B 8K per chunk
constexpr int NSTG = 4;
constexpr int DSMEM = NSTG * STAGE;          // 65536 B -> 2 CTAs/SM

// ---------------- device scratch --------------------
__device__ __align__(16) unsigned g_FA[8192 * 32 * 4];    // 4 MB
__device__ __align__(16) unsigned g_FB[16384 * 32 * 2];   // 4 MB
__device__ __align__(16) unsigned short g_dt [(size_t)BSZ * BSZ];   // delta[i][j], 8 MB
__device__ __align__(16) unsigned short g_dtT[(size_t)BSZ * BSZ];   // delta[j][i], 8 MB
__device__ unsigned g_pos[BSZ];              // (lower_bound(li) << 16) | last_index(<= li)
__device__ int g_cdf[257];                   // cdf[b] = #sorted labels < b/256
__device__ float g_S[BSZ];
__device__ float g_sorted[BSZ];
__device__ float g_u[NTOT];
__device__ float g_p[NTOT];

// ---------------- PTX helpers -----------------------
__device__ __forceinline__ uint32_t smem_u32(const void* p) {
    uint32_t a;
    asm("{ .reg .u64 t; cvta.to.shared.u64 t, %1; cvt.u32.u64 %0, t; }" : "=r"(a) : "l"(p));
    return a;
}
__device__ __forceinline__ void cpa16(uint32_t d, const void* s) {
    asm volatile("cp.async.cg.shared.global [%0], [%1], 16;" :: "r"(d), "l"(s) : "memory");
}
#define CP_COMMIT() asm volatile("cp.async.commit_group;" ::: "memory")
#define CP_WAIT0()  asm volatile("cp.async.wait_group 0;" ::: "memory")
#define CP_WAIT1()  asm volatile("cp.async.wait_group 1;" ::: "memory")
#define CP_WAIT2()  asm volatile("cp.async.wait_group 2;" ::: "memory")
__device__ __forceinline__ void mma_f16(float* c, const uint32_t* a, const uint32_t* b) {
    asm volatile("mma.sync.aligned.m16n8k16.row.col.f32.f16.f16.f32 "
        "{%0,%1,%2,%3}, {%4,%5,%6,%7}, {%8,%9}, {%0,%1,%2,%3};"
        : "+f"(c[0]), "+f"(c[1]), "+f"(c[2]), "+f"(c[3])
        : "r"(a[0]), "r"(a[1]), "r"(a[2]), "r"(a[3]), "r"(b[0]), "r"(b[1]));
}

// ---------------- K0: fp16 scatter (blocks 1..768) + sort/pos/cdf (block 0) --
__device__ __forceinline__ float ld_feat(const float* feats, int row, int col) {
    int b = row & (BSZ - 1), v = row >> 11;
    return feats[(size_t)((b << 1) | v) * DIM + col];
}
__device__ __forceinline__ unsigned pack2(const float* feats, int row, int col) {
    __half2 h = __floats2half2_rn(ld_feat(feats, row, col), ld_feat(feats, row, col + 1));
    return *(unsigned*)&h;
}
__global__ __launch_bounds__(1024) void k_prep(const float* __restrict__ feats,
                                               const float* __restrict__ labels) {
    __shared__ float s[BSZ];
    if (blockIdx.x == 0) {
        // ---- label sort + per-label positions + bucket CDF (1024 threads) ----
        int tid = threadIdx.x;
        s[tid] = labels[tid]; s[tid + 1024] = labels[tid + 1024];
        __syncthreads();
        for (int k = 2; k <= BSZ; k <<= 1)
            for (int j = k >> 1; j > 0; j >>= 1) {
                for (int i = tid; i < BSZ; i += 1024) {
                    int ixj = i ^ j;
                    if (ixj > i) {
                        bool up = ((i & k) == 0);
                        float a = s[i], bb = s[ixj];
                        if ((a > bb) == up) { s[i] = bb; s[ixj] = a; }
                    }
                }
                __syncthreads();
            }
        g_sorted[tid] = s[tid]; g_sorted[tid + 1024] = s[tid + 1024];
        // per-label sorted positions: p = first index >= li, q-1 = last index <= li
        for (int ib = tid; ib < BSZ; ib += 1024) {
            float li = labels[ib];
            int p = 0, q = 0;
#pragma unroll
            for (int st = 2048; st; st >>= 1) {
                int np = p + st, nq = q + st;
                if (np <= BSZ && s[np - 1] <  li) p = np;
                if (nq <= BSZ && s[nq - 1] <= li) q = nq;
            }
            g_pos[ib] = ((unsigned)p << 16) | (unsigned)(q - 1);
        }
        // bucket CDF: cdf[b] = count(s < b/256), b in [0,256]
        if (tid <= 256) {
            float thr = (float)tid * 0.00390625f;
            int q = 0;
#pragma unroll
            for (int st = 2048; st; st >>= 1) {
                int nq = q + st;
                if (nq <= BSZ && s[nq - 1] < thr) q = nq;
            }
            g_cdf[tid] = q;
        }
        return;
    }
    // ---- fragment-major fp16 scatter (blocks 1..768, 1024 threads) ----
    int tid = (blockIdx.x - 1) * 1024 + threadIdx.x;   // 0..786431
    if (tid < NTOT) { g_u[tid] = 0.f; g_p[tid] = 0.f; }
    int gw = tid >> 5;           // warp id 0..24575
    int l  = tid & 31;
    int g  = l >> 2, tg = l & 3;
    if (gw < 8192) {
        int sA = gw & 1, t = (gw >> 1) & 7, ch = (gw >> 4) & 15, rg = gw >> 8;
        int R = rg * 128 + t * 16 + g;
        int C = ch * 32 + sA * 16 + tg * 2;
        uint4 o;
        o.x = pack2(feats, R,     C);
        o.y = pack2(feats, R + 8, C);
        o.z = pack2(feats, R,     C + 8);
        o.w = pack2(feats, R + 8, C + 8);
        ((uint4*)g_FA)[(size_t)gw * 32 + l] = o;
    } else {
        int w2 = gw - 8192;
        int sB = w2 & 1, n8 = (w2 >> 1) & 15, ch = (w2 >> 5) & 15, ng = w2 >> 9;
        int J = ng * 128 + n8 * 8 + g;
        int K = ch * 32 + sB * 16 + tg * 2;
        uint2 o;
        o.x = pack2(feats, J, K);
        o.y = pack2(feats, J, K + 8);
        ((uint2*)g_FB)[(size_t)w2 * 32 + l] = o;
    }
}

// ---------------- K2: delta^T table (uint16) + S row sums --------------------
// Bucketed mirrored-boundary search: integer bucket of mir narrows the binary
// search to ~8 elements; predicates identical to the full search (exact).
__global__ void k_tab(const float* __restrict__ labels) {
    __shared__ float s[BSZ];
    __shared__ int cdf[257];
    __shared__ float red[256];
    int tid = threadIdx.x;
    int jb  = blockIdx.x;
    for (int m = tid; m < BSZ; m += 256) s[m] = g_sorted[m];
    if (tid < 256) cdf[tid] = g_cdf[tid];
    if (tid == 0)  cdf[256] = g_cdf[256];
    __syncthreads();
    float c = labels[jb];
    float rs = 0.f;
    unsigned short* orow = g_dtT + (size_t)jb * BSZ;
#pragma unroll 1
    for (int it = 0; it < 4; it++) {
        int ib0 = tid + it * 512;
        int ib1 = ib0 + 256;
        float li0 = labels[ib0], li1 = labels[ib1];
        float d0 = c - li0, d1 = c - li1;
        rs += expf(-0.5f * d0 * d0) + expf(-0.5f * d1 * d1);
        float mir0 = c + d0, mir1 = c + d1;
        bool le0 = d0 > 0.f, le1 = d1 > 0.f;   // true: count(<= mir) -> right bound
        // exact bucket of mir (ALU-only adjust guards float-mul rounding)
        int b0 = (int)(mir0 * 256.f); b0 = b0 < 0 ? 0 : (b0 > 255 ? 255 : b0);
        while (b0 < 255 && (float)(b0 + 1) * 0.00390625f <= mir0) b0++;
        while (b0 > 0   && (float)b0       * 0.00390625f >  mir0) b0--;
        int b1 = (int)(mir1 * 256.f); b1 = b1 < 0 ? 0 : (b1 > 255 ? 255 : b1);
        while (b1 < 255 && (float)(b1 + 1) * 0.00390625f <= mir1) b1++;
        while (b1 > 0   && (float)b1       * 0.00390625f >  mir1) b1--;
        int l0 = cdf[b0], h0 = cdf[b0 + 1];
        int l1 = cdf[b1], h1 = cdf[b1 + 1];
#pragma unroll 1
        while (l0 < h0 || l1 < h1) {
            if (l0 < h0) { int mid = (l0 + h0) >> 1; float v = s[mid];
                           bool p = le0 ? (v <= mir0) : (v < mir0);
                           if (p) l0 = mid + 1; else h0 = mid; }
            if (l1 < h1) { int mid = (l1 + h1) >> 1; float v = s[mid];
                           bool p = le1 ? (v <= mir1) : (v < mir1);
                           if (p) l1 = mid + 1; else h1 = mid; }
        }
        int q0 = l0, q1 = l1;
        unsigned pos0 = g_pos[ib0], pos1 = g_pos[ib1];
        int L0 = le0 ? (int)(pos0 >> 16) : q0;
        int R0 = le0 ? (q0 - 1)          : (int)(pos0 & 0xFFFFu);
        int L1 = le1 ? (int)(pos1 >> 16) : q1;
        int R1 = le1 ? (q1 - 1)          : (int)(pos1 & 0xFFFFu);
        orow[ib0] = (unsigned short)(VIEWS * (BSZ - (R0 - L0 + 1)));
        orow[ib1] = (unsigned short)(VIEWS * (BSZ - (R1 - L1 + 1)));
    }
    red[tid] = rs; __syncthreads();
    for (int st = 128; st > 0; st >>= 1) { if (tid < st) red[tid] += red[tid + st]; __syncthreads(); }
    if (tid == 0) g_S[jb] = ((float)VIEWS * red[0] - 1.0f) * RSQRT2PI;
}

// ---------------- K2b: transpose delta^T -> delta (ushort) -------------------
__global__ void k_transp() {
    __shared__ unsigned short tile[64][72];
    int bx = blockIdx.x & 31, by = blockIdx.x >> 5;
    int r  = threadIdx.x >> 2;
    int c0 = (threadIdx.x & 3) * 16;
    const unsigned short* src = g_dtT + (size_t)(by * 64 + r) * BSZ + bx * 64 + c0;
    *(uint4*)&tile[r][c0]     = *(const uint4*)src;
    *(uint4*)&tile[r][c0 + 8] = *(const uint4*)(src + 8);
    __syncthreads();
    unsigned short ov[16];
#pragma unroll
    for (int k = 0; k < 16; k++) ov[k] = tile[c0 + k][r];
    unsigned short* dst = g_dt + (size_t)(bx * 64 + r) * BSZ + by * 64 + c0;
    *(uint4*)dst       = *(const uint4*)ov;
    *(uint4*)(dst + 8) = *(const uint4*)(ov + 8);
}

// ---------------- K3: fp16 mma.sync GEMM + fused epilogue --------------------
__global__ __launch_bounds__(256, 2) void k_main(const float* __restrict__ labels) {
    extern __shared__ __align__(16) char smem[];
    __shared__ float uRow[128], pRow[128], uCol[128], pCol[128];
    __shared__ float slabA[128], slabB[128];
    uint32_t sb = smem_u32(smem);
    int tid = threadIdx.x, wid = tid >> 5, lane = tid & 31;

    // triangular tile index
    int t  = blockIdx.x;
    int bi = (int)((sqrtf(8.f * (float)t + 1.f) - 1.f) * 0.5f);
    while ((bi + 1) * (bi + 2) / 2 <= t) bi++;
    while (bi * (bi + 1) / 2 > t) bi--;
    int bj = t - bi * (bi + 1) / 2;
    int i0 = bi * 128, j0 = bj * 128;
    bool diag = (bi == bj);

    if (tid < 128) {
        uRow[tid] = 0.f; pRow[tid] = 0.f; uCol[tid] = 0.f; pCol[tid] = 0.f;
        slabA[tid] = labels[(i0 + tid) & (BSZ - 1)];
        slabB[tid] = labels[(j0 + tid) & (BSZ - 1)];
    }

    const char* Ab = (const char*)g_FA + (size_t)(i0 >> 7) * 131072;
    const char* Bb = (const char*)g_FB + (size_t)(j0 >> 7) * 131072;

    auto issue = [&](int c, int si) {
        uint32_t stg = sb + (uint32_t)si * STAGE;
        const char* As = Ab + (size_t)c * 8192;
        const char* Bs = Bb + (size_t)c * 8192;
        cpa16(stg + tid * 16,          As + tid * 16);
        cpa16(stg + 4096 + tid * 16,   As + 4096 + tid * 16);
        cpa16(stg + 8192 + tid * 16,   Bs + tid * 16);
        cpa16(stg + 12288 + tid * 16,  Bs + 4096 + tid * 16);
        CP_COMMIT();
    };

    int wr = wid & 1, wc = wid >> 1;   // warp tile 64 rows x 32 cols

    float acc[4][4][4];
#pragma unroll
    for (int mt = 0; mt < 4; mt++)
#pragma unroll
        for (int nt = 0; nt < 4; nt++)
#pragma unroll
            for (int e = 0; e < 4; e++) acc[mt][nt][e] = 0.f;

    issue(0, 0); issue(1, 1); issue(2, 2);
    int stc = 0;
#pragma unroll 1
    for (int c = 0; c < NCHUNK; c++) {
        if (c < NCHUNK - 2)      { CP_WAIT2(); }
        else if (c == NCHUNK - 2){ CP_WAIT1(); }
        else                     { CP_WAIT0(); }
        __syncthreads();
        if (c + 3 < NCHUNK) {
            int si = stc + 3; if (si >= NSTG) si -= NSTG;
            issue(c + 3, si);
        }
        uint32_t stg = sb + (uint32_t)stc * STAGE;
#pragma unroll
        for (int s = 0; s < 2; s++) {
            uint32_t a[4][4], b[4][2];
#pragma unroll
            for (int mt = 0; mt < 4; mt++) {
                int tt = wr * 4 + mt;
                uint32_t ad = stg + (uint32_t)((tt * 2 + s) * 512 + lane * 16);
                asm volatile("ld.shared.v4.b32 {%0,%1,%2,%3}, [%4];"
                    : "=r"(a[mt][0]), "=r"(a[mt][1]), "=r"(a[mt][2]), "=r"(a[mt][3]) : "r"(ad));
            }
#pragma unroll
            for (int nt = 0; nt < 4; nt++) {
                int n8 = wc * 4 + nt;
                uint32_t bd = stg + 8192u + (uint32_t)((n8 * 2 + s) * 256 + lane * 8);
                asm volatile("ld.shared.v2.b32 {%0,%1}, [%2];"
                    : "=r"(b[nt][0]), "=r"(b[nt][1]) : "r"(bd));
            }
#pragma unroll
            for (int mt = 0; mt < 4; mt++)
#pragma unroll
                for (int nt = 0; nt < 4; nt++)
                    mma_f16(acc[mt][nt], a[mt], b[nt]);
        }
        stc = (stc == NSTG - 1) ? 0 : stc + 1;
    }

    // ---- fused epilogue (u16 delta tables + on-the-fly mask) ----
    const float invT = 1.0f / TEMP;
    float uR[8], pR[8], uC[8], pC[8];
#pragma unroll
    for (int e = 0; e < 8; e++) { uR[e] = 0.f; pR[e] = 0.f; uC[e] = 0.f; pC[e] = 0.f; }
    int rq = lane >> 2, cq = 2 * (lane & 3);
#pragma unroll
    for (int mt = 0; mt < 4; mt++) {
#pragma unroll
        for (int h = 0; h < 2; h++) {
            int r  = wr * 64 + mt * 16 + rq + h * 8;
            int iB = (i0 + r) & (BSZ - 1);
            float li = slabA[r];
            const unsigned short* dtrow = g_dt  + (size_t)iB * BSZ;
            const unsigned short* dTrow = g_dtT + (size_t)iB * BSZ;
            int ridx = mt * 2 + h;
#pragma unroll
            for (int nt = 0; nt < 4; nt++) {
                int c2  = wc * 32 + nt * 8 + cq;
                int jB2 = (j0 + c2) & (BSZ - 1);
                uint32_t dp  = *(const uint32_t*)(dtrow + jB2);
                uint32_t dTp = *(const uint32_t*)(dTrow + jB2);
#pragma unroll
                for (int e = 0; e < 2; e++) {
                    int cc = c2 + e;
                    float a = acc[mt][nt][h * 2 + e];
                    float x = fmaf(a, invT, -invT);
                    float lj = slabB[cc];
                    float dd = li - lj;
                    float m  = __expf(-0.5f * dd * dd) * RSQRT2PI;
                    float ex = __expf(x);
                    float dv  = (float)((e ? (dp >> 16)  : dp)  & 0xFFFF);
                    float dTv = (float)((e ? (dTp >> 16) : dTp) & 0xFFFF);
                    bool skip = diag && (r == cc);
                    if (!skip) {
                        uR[ridx] = fmaf(ex, dv, uR[ridx]);
                        pR[ridx] = fmaf(m, x, pR[ridx]);
                        if (!diag) {
                            int cidx = nt * 2 + e;
                            uC[cidx] = fmaf(ex, dTv, uC[cidx]);
                            pC[cidx] = fmaf(m, x, pC[cidx]);
                        }
                    }
                }
            }
        }
    }
#pragma unroll
    for (int mt = 0; mt < 4; mt++)
#pragma unroll
        for (int h = 0; h < 2; h++) {
            int r = wr * 64 + mt * 16 + rq + h * 8;
            atomicAdd(&uRow[r], uR[mt * 2 + h]);
            atomicAdd(&pRow[r], pR[mt * 2 + h]);
        }
    if (!diag) {
#pragma unroll
        for (int nt = 0; nt < 4; nt++)
#pragma unroll
            for (int e = 0; e < 2; e++) {
                int cc = wc * 32 + nt * 8 + cq + e;
                atomicAdd(&uCol[cc], uC[nt * 2 + e]);
                atomicAdd(&pCol[cc], pC[nt * 2 + e]);
            }
    }
    __syncthreads();
    if (tid < 128) {
        atomicAdd(&g_u[i0 + tid], uRow[tid]);
        atomicAdd(&g_p[i0 + tid], pRow[tid]);
        if (!diag) {
            atomicAdd(&g_u[j0 + tid], uCol[tid]);
            atomicAdd(&g_p[j0 + tid], pCol[tid]);
        }
    }
}

// ---------------- K4: final reduction -----------------------------------------
__global__ void k_final(float* __restrict__ out) {
    __shared__ float red[512];
    int tid = threadIdx.x;
    float sum = 0.f;
    for (int i = tid; i < NTOT; i += 512) {
        float lp = g_p[i] / g_S[i & (BSZ - 1)] - logf(g_u[i]);
        sum += lp;
    }
    red[tid] = sum; __syncthreads();
    for (int st = 256; st > 0; st >>= 1) { if (tid < st) red[tid] += red[tid + st]; __syncthreads(); }
    if (tid == 0) out[0] = -red[0] / (float)NTOT;
}

// ---------------- entry --------------------------------------------------------
extern "C" void kernel_launch(void* const* d_in, const int* in_sizes, int n_in,
                              void* d_out, int out_size) {
    (void)in_sizes; (void)n_in; (void)out_size;
    const float* feats  = (const float*)d_in[0];
    const float* labels = (const float*)d_in[1];
    float* out = (float*)d_out;

    cudaFuncSetAttribute(k_main, cudaFuncAttributeMaxDynamicSharedMemorySize, DSMEM);

    k_prep  <<<769, 1024>>>(feats, labels);
    k_tab   <<<2048, 256>>>(labels);
    k_transp<<<1024, 256>>>();
    k_main  <<<528, 256, DSMEM>>>(labels);
    k_final <<<1, 512>>>(out);
}

// round 11
// speedup vs baseline: 1.7865x; 1.1237x over previous
#include <cuda_runtime.h>
#include <cuda_fp16.h>
#include <cstdint>
#include <math.h>

// ---------------- problem constants ----------------
constexpr int BSZ   = 2048;
constexpr int VIEWS = 2;
constexpr int DIM   = 512;
constexpr int NTOT  = BSZ * VIEWS;          // 4096
constexpr float TEMP = 0.07f;
constexpr float RSQRT2PI = 0.3989422804014327f;

// GEMM tiling: 128x128 CTA tile, 8 warps of 64x32, fp16 m16n8k16, K-chunks of 64
constexpr int KC = 64;
constexpr int NCHUNK = DIM / KC;             // 8
constexpr int STAGE = 32768;                 // A 16K + B 16K per chunk
constexpr int NSTG = 3;
constexpr int DSMEM = NSTG * STAGE;          // 98304 B -> 2 CTAs/SM (192K + static < 228K)

// ---------------- device scratch --------------------
__device__ __align__(16) unsigned g_FA[8192 * 32 * 4];    // 4 MB
__device__ __align__(16) unsigned g_FB[16384 * 32 * 2];   // 4 MB
__device__ __align__(16) unsigned short g_dt [(size_t)BSZ * BSZ];   // delta[i][j], 8 MB
__device__ __align__(16) unsigned short g_dtT[(size_t)BSZ * BSZ];   // delta[j][i], 8 MB
__device__ unsigned g_pos[BSZ];              // (lower_bound(li) << 16) | last_index(<= li)
__device__ int g_cdf[257];                   // cdf[b] = #sorted labels < b/256
__device__ float g_S[BSZ];
__device__ float g_sorted[BSZ];
__device__ float g_u[NTOT];
__device__ float g_p[NTOT];

// ---------------- PTX helpers -----------------------
__device__ __forceinline__ uint32_t smem_u32(const void* p) {
    uint32_t a;
    asm("{ .reg .u64 t; cvta.to.shared.u64 t, %1; cvt.u32.u64 %0, t; }" : "=r"(a) : "l"(p));
    return a;
}
__device__ __forceinline__ void cpa16(uint32_t d, const void* s) {
    asm volatile("cp.async.cg.shared.global [%0], [%1], 16;" :: "r"(d), "l"(s) : "memory");
}
#define CP_COMMIT() asm volatile("cp.async.commit_group;" ::: "memory")
#define CP_WAIT0()  asm volatile("cp.async.wait_group 0;" ::: "memory")
#define CP_WAIT1()  asm volatile("cp.async.wait_group 1;" ::: "memory")
__device__ __forceinline__ void mma_f16(float* c, const uint32_t* a, const uint32_t* b) {
    asm volatile("mma.sync.aligned.m16n8k16.row.col.f32.f16.f16.f32 "
        "{%0,%1,%2,%3}, {%4,%5,%6,%7}, {%8,%9}, {%0,%1,%2,%3};"
        : "+f"(c[0]), "+f"(c[1]), "+f"(c[2]), "+f"(c[3])
        : "r"(a[0]), "r"(a[1]), "r"(a[2]), "r"(a[3]), "r"(b[0]), "r"(b[1]));
}

// ---------------- K0: fp16 scatter (blocks 1..768) + sort/pos/cdf (block 0) --
__device__ __forceinline__ float ld_feat(const float* feats, int row, int col) {
    int b = row & (BSZ - 1), v = row >> 11;
    return feats[(size_t)((b << 1) | v) * DIM + col];
}
__device__ __forceinline__ unsigned pack2(const float* feats, int row, int col) {
    __half2 h = __floats2half2_rn(ld_feat(feats, row, col), ld_feat(feats, row, col + 1));
    return *(unsigned*)&h;
}
__global__ __launch_bounds__(1024) void k_prep(const float* __restrict__ feats,
                                               const float* __restrict__ labels) {
    __shared__ float s[BSZ];
    if (blockIdx.x == 0) {
        // ---- label sort (hybrid bitonic: smem phases j>=64, warp phases j<=32) ----
        int tid = threadIdx.x;
        int lane = tid & 31, warp = tid >> 5;       // 32 warps x 64 elements
        int base = warp * 64;
        int i0 = base + lane, i1 = i0 + 32;
        s[tid] = labels[tid]; s[tid + 1024] = labels[tid + 1024];
        __syncthreads();
        // stage A: k = 2..64 entirely in registers
        {
            float v0 = s[i0], v1 = s[i1];
#pragma unroll
            for (int k = 2; k <= 64; k <<= 1) {
#pragma unroll
                for (int j = k >> 1; j >= 1; j >>= 1) {
                    if (j == 32) {
                        bool up = ((i0 & k) == 0);
                        float lo = fminf(v0, v1), hi = fmaxf(v0, v1);
                        v0 = up ? lo : hi; v1 = up ? hi : lo;
                    } else {
                        bool up0 = ((i0 & k) == 0), up1 = ((i1 & k) == 0);
                        bool upper = (lane & j) != 0;
                        float p0 = __shfl_xor_sync(0xffffffffu, v0, j);
                        float p1 = __shfl_xor_sync(0xffffffffu, v1, j);
                        v0 = (up0 ^ upper) ? fminf(v0, p0) : fmaxf(v0, p0);
                        v1 = (up1 ^ upper) ? fminf(v1, p1) : fmaxf(v1, p1);
                    }
                }
            }
            s[i0] = v0; s[i1] = v1;
        }
        __syncthreads();
        // stages k = 128..2048
        for (int k = 128; k <= 2048; k <<= 1) {
            for (int j = k >> 1; j >= 64; j >>= 1) {
                for (int i = tid; i < BSZ; i += 1024) {
                    int ixj = i ^ j;
                    if (ixj > i) {
                        bool up = ((i & k) == 0);
                        float a = s[i], b = s[ixj];
                        if ((a > b) == up) { s[i] = b; s[ixj] = a; }
                    }
                }
                __syncthreads();
            }
            // register session: j = 32,16,8,4,2,1 (up uniform per 64-block)
            {
                float v0 = s[i0], v1 = s[i1];
                bool up = ((i0 & k) == 0);
                float lo = fminf(v0, v1), hi = fmaxf(v0, v1);
                v0 = up ? lo : hi; v1 = up ? hi : lo;
#pragma unroll
                for (int j = 16; j >= 1; j >>= 1) {
                    bool upper = (lane & j) != 0;
                    float p0 = __shfl_xor_sync(0xffffffffu, v0, j);
                    float p1 = __shfl_xor_sync(0xffffffffu, v1, j);
                    v0 = (up ^ upper) ? fminf(v0, p0) : fmaxf(v0, p0);
                    v1 = (up ^ upper) ? fminf(v1, p1) : fmaxf(v1, p1);
                }
                s[i0] = v0; s[i1] = v1;
            }
            __syncthreads();
        }
        g_sorted[tid] = s[tid]; g_sorted[tid + 1024] = s[tid + 1024];
        // per-label sorted positions: p = first index >= li, q-1 = last index <= li
        for (int ib = tid; ib < BSZ; ib += 1024) {
            float li = labels[ib];
            int p = 0, q = 0;
#pragma unroll
            for (int st = 2048; st; st >>= 1) {
                int np = p + st, nq = q + st;
                if (np <= BSZ && s[np - 1] <  li) p = np;
                if (nq <= BSZ && s[nq - 1] <= li) q = nq;
            }
            g_pos[ib] = ((unsigned)p << 16) | (unsigned)(q - 1);
        }
        // bucket CDF: cdf[b] = count(s < b/256), b in [0,256]
        if (tid <= 256) {
            float thr = (float)tid * 0.00390625f;
            int q = 0;
#pragma unroll
            for (int st = 2048; st; st >>= 1) {
                int nq = q + st;
                if (nq <= BSZ && s[nq - 1] < thr) q = nq;
            }
            g_cdf[tid] = q;
        }
        return;
    }
    // ---- fragment-major fp16 scatter (blocks 1..768, 1024 threads) ----
    int tid = (blockIdx.x - 1) * 1024 + threadIdx.x;   // 0..786431
    if (tid < NTOT) { g_u[tid] = 0.f; g_p[tid] = 0.f; }
    int gw = tid >> 5;           // warp id 0..24575
    int l  = tid & 31;
    int g  = l >> 2, tg = l & 3;
    if (gw < 8192) {
        int sA = gw & 1, t = (gw >> 1) & 7, ch = (gw >> 4) & 15, rg = gw >> 8;
        int R = rg * 128 + t * 16 + g;
        int C = ch * 32 + sA * 16 + tg * 2;
        uint4 o;
        o.x = pack2(feats, R,     C);
        o.y = pack2(feats, R + 8, C);
        o.z = pack2(feats, R,     C + 8);
        o.w = pack2(feats, R + 8, C + 8);
        ((uint4*)g_FA)[(size_t)gw * 32 + l] = o;
    } else {
        int w2 = gw - 8192;
        int sB = w2 & 1, n8 = (w2 >> 1) & 15, ch = (w2 >> 5) & 15, ng = w2 >> 9;
        int J = ng * 128 + n8 * 8 + g;
        int K = ch * 32 + sB * 16 + tg * 2;
        uint2 o;
        o.x = pack2(feats, J, K);
        o.y = pack2(feats, J, K + 8);
        ((uint2*)g_FB)[(size_t)w2 * 32 + l] = o;
    }
}

// ---------------- K2: delta^T table (uint16) + S row sums --------------------
__global__ void k_tab(const float* __restrict__ labels) {
    __shared__ float s[BSZ];
    __shared__ int cdf[257];
    __shared__ float red[256];
    int tid = threadIdx.x;
    int jb  = blockIdx.x;
    for (int m = tid; m < BSZ; m += 256) s[m] = g_sorted[m];
    if (tid < 256) cdf[tid] = g_cdf[tid];
    if (tid == 0)  cdf[256] = g_cdf[256];
    __syncthreads();
    float c = labels[jb];
    float rs = 0.f;
    unsigned short* orow = g_dtT + (size_t)jb * BSZ;
#pragma unroll 1
    for (int it = 0; it < 4; it++) {
        int ib0 = tid + it * 512;
        int ib1 = ib0 + 256;
        float li0 = labels[ib0], li1 = labels[ib1];
        float d0 = c - li0, d1 = c - li1;
        rs += expf(-0.5f * d0 * d0) + expf(-0.5f * d1 * d1);
        float mir0 = c + d0, mir1 = c + d1;
        bool le0 = d0 > 0.f, le1 = d1 > 0.f;   // true: count(<= mir) -> right bound
        int b0 = (int)(mir0 * 256.f); b0 = b0 < 0 ? 0 : (b0 > 255 ? 255 : b0);
        while (b0 < 255 && (float)(b0 + 1) * 0.00390625f <= mir0) b0++;
        while (b0 > 0   && (float)b0       * 0.00390625f >  mir0) b0--;
        int b1 = (int)(mir1 * 256.f); b1 = b1 < 0 ? 0 : (b1 > 255 ? 255 : b1);
        while (b1 < 255 && (float)(b1 + 1) * 0.00390625f <= mir1) b1++;
        while (b1 > 0   && (float)b1       * 0.00390625f >  mir1) b1--;
        int l0 = cdf[b0], h0 = cdf[b0 + 1];
        int l1 = cdf[b1], h1 = cdf[b1 + 1];
#pragma unroll 1
        while (l0 < h0 || l1 < h1) {
            if (l0 < h0) { int mid = (l0 + h0) >> 1; float v = s[mid];
                           bool p = le0 ? (v <= mir0) : (v < mir0);
                           if (p) l0 = mid + 1; else h0 = mid; }
            if (l1 < h1) { int mid = (l1 + h1) >> 1; float v = s[mid];
                           bool p = le1 ? (v <= mir1) : (v < mir1);
                           if (p) l1 = mid + 1; else h1 = mid; }
        }
        int q0 = l0, q1 = l1;
        unsigned pos0 = g_pos[ib0], pos1 = g_pos[ib1];
        int L0 = le0 ? (int)(pos0 >> 16) : q0;
        int R0 = le0 ? (q0 - 1)          : (int)(pos0 & 0xFFFFu);
        int L1 = le1 ? (int)(pos1 >> 16) : q1;
        int R1 = le1 ? (q1 - 1)          : (int)(pos1 & 0xFFFFu);
        orow[ib0] = (unsigned short)(VIEWS * (BSZ - (R0 - L0 + 1)));
        orow[ib1] = (unsigned short)(VIEWS * (BSZ - (R1 - L1 + 1)));
    }
    red[tid] = rs; __syncthreads();
    for (int st = 128; st > 0; st >>= 1) { if (tid < st) red[tid] += red[tid + st]; __syncthreads(); }
    if (tid == 0) g_S[jb] = ((float)VIEWS * red[0] - 1.0f) * RSQRT2PI;
}

// ---------------- K2b: transpose delta^T -> delta (ushort) -------------------
__global__ void k_transp() {
    __shared__ unsigned short tile[64][72];
    int bx = blockIdx.x & 31, by = blockIdx.x >> 5;
    int r  = threadIdx.x >> 2;
    int c0 = (threadIdx.x & 3) * 16;
    const unsigned short* src = g_dtT + (size_t)(by * 64 + r) * BSZ + bx * 64 + c0;
    *(uint4*)&tile[r][c0]     = *(const uint4*)src;
    *(uint4*)&tile[r][c0 + 8] = *(const uint4*)(src + 8);
    __syncthreads();
    unsigned short ov[16];
#pragma unroll
    for (int k = 0; k < 16; k++) ov[k] = tile[c0 + k][r];
    unsigned short* dst = g_dt + (size_t)(bx * 64 + r) * BSZ + by * 64 + c0;
    *(uint4*)dst       = *(const uint4*)ov;
    *(uint4*)(dst + 8) = *(const uint4*)(ov + 8);
}

// ---------------- K3: fp16 mma.sync GEMM + fused epilogue --------------------
__global__ __launch_bounds__(256, 2) void k_main(const float* __restrict__ labels) {
    extern __shared__ __align__(16) char smem[];
    __shared__ float uRow[128], pRow[128], uCol[128], pCol[128];
    __shared__ float slabA[128], slabB[128];
    uint32_t sb = smem_u32(smem);
    int tid = threadIdx.x, wid = tid >> 5, lane = tid & 31;

    // triangular tile index
    int t  = blockIdx.x;
    int bi = (int)((sqrtf(8.f * (float)t + 1.f) - 1.f) * 0.5f);
    while ((bi + 1) * (bi + 2) / 2 <= t) bi++;
    while (bi * (bi + 1) / 2 > t) bi--;
    int bj = t - bi * (bi + 1) / 2;
    int i0 = bi * 128, j0 = bj * 128;
    bool diag = (bi == bj);

    if (tid < 128) {
        uRow[tid] = 0.f; pRow[tid] = 0.f; uCol[tid] = 0.f; pCol[tid] = 0.f;
        slabA[tid] = labels[(i0 + tid) & (BSZ - 1)];
        slabB[tid] = labels[(j0 + tid) & (BSZ - 1)];
    }

    const char* Ab = (const char*)g_FA + (size_t)(i0 >> 7) * 131072;
    const char* Bb = (const char*)g_FB + (size_t)(j0 >> 7) * 131072;

    auto issue = [&](int c, int si) {
        uint32_t stg = sb + (uint32_t)si * STAGE;
        const char* As = Ab + (size_t)c * 16384;
        const char* Bs = Bb + (size_t)c * 16384;
#pragma unroll
        for (int q = 0; q < 4; q++) {
            cpa16(stg + q * 4096 + tid * 16,          As + q * 4096 + tid * 16);
            cpa16(stg + 16384 + q * 4096 + tid * 16,  Bs + q * 4096 + tid * 16);
        }
        CP_COMMIT();
    };

    int wr = wid & 1, wc = wid >> 1;   // warp tile 64 rows x 32 cols

    float acc[4][4][4];
#pragma unroll
    for (int mt = 0; mt < 4; mt++)
#pragma unroll
        for (int nt = 0; nt < 4; nt++)
#pragma unroll
            for (int e = 0; e < 4; e++) acc[mt][nt][e] = 0.f;

    issue(0, 0); issue(1, 1);
    int stc = 0;
#pragma unroll 1
    for (int c = 0; c < NCHUNK; c++) {
        if (c < NCHUNK - 1) { CP_WAIT1(); } else { CP_WAIT0(); }
        __syncthreads();
        if (c + 2 < NCHUNK) {
            int si = stc + 2; if (si >= NSTG) si -= NSTG;
            issue(c + 2, si);
        }
        uint32_t stg = sb + (uint32_t)stc * STAGE;
#pragma unroll
        for (int s = 0; s < 4; s++) {
            int q = s >> 1, ss = s & 1;
            uint32_t a[4][4], b[4][2];
#pragma unroll
            for (int mt = 0; mt < 4; mt++) {
                int tt = wr * 4 + mt;
                uint32_t ad = stg + (uint32_t)(q * 8192 + (tt * 2 + ss) * 512 + lane * 16);
                asm volatile("ld.shared.v4.b32 {%0,%1,%2,%3}, [%4];"
                    : "=r"(a[mt][0]), "=r"(a[mt][1]), "=r"(a[mt][2]), "=r"(a[mt][3]) : "r"(ad));
            }
#pragma unroll
            for (int nt = 0; nt < 4; nt++) {
                int n8 = wc * 4 + nt;
                uint32_t bd = stg + 16384u + (uint32_t)(q * 8192 + (n8 * 2 + ss) * 256 + lane * 8);
                asm volatile("ld.shared.v2.b32 {%0,%1}, [%2];"
                    : "=r"(b[nt][0]), "=r"(b[nt][1]) : "r"(bd));
            }
#pragma unroll
            for (int mt = 0; mt < 4; mt++)
#pragma unroll
                for (int nt = 0; nt < 4; nt++)
                    mma_f16(acc[mt][nt], a[mt], b[nt]);
        }
        stc = (stc == NSTG - 1) ? 0 : stc + 1;
    }

    // ---- fused epilogue (u16 delta tables + on-the-fly mask) ----
    const float invT = 1.0f / TEMP;
    float uR[8], pR[8], uC[8], pC[8];
#pragma unroll
    for (int e = 0; e < 8; e++) { uR[e] = 0.f; pR[e] = 0.f; uC[e] = 0.f; pC[e] = 0.f; }
    int rq = lane >> 2, cq = 2 * (lane & 3);
#pragma unroll
    for (int mt = 0; mt < 4; mt++) {
#pragma unroll
        for (int h = 0; h < 2; h++) {
            int r  = wr * 64 + mt * 16 + rq + h * 8;
            int iB = (i0 + r) & (BSZ - 1);
            float li = slabA[r];
            const unsigned short* dtrow = g_dt  + (size_t)iB * BSZ;
            const unsigned short* dTrow = g_dtT + (size_t)iB * BSZ;
            int ridx = mt * 2 + h;
#pragma unroll
            for (int nt = 0; nt < 4; nt++) {
                int c2  = wc * 32 + nt * 8 + cq;
                int jB2 = (j0 + c2) & (BSZ - 1);
                uint32_t dp  = *(const uint32_t*)(dtrow + jB2);
                uint32_t dTp = *(const uint32_t*)(dTrow + jB2);
#pragma unroll
                for (int e = 0; e < 2; e++) {
                    int cc = c2 + e;
                    float a = acc[mt][nt][h * 2 + e];
                    float x = fmaf(a, invT, -invT);
                    float lj = slabB[cc];
                    float dd = li - lj;
                    float m  = __expf(-0.5f * dd * dd) * RSQRT2PI;
                    float ex = __expf(x);
                    float dv  = (float)((e ? (dp >> 16)  : dp)  & 0xFFFF);
                    float dTv = (float)((e ? (dTp >> 16) : dTp) & 0xFFFF);
                    bool skip = diag && (r == cc);
                    if (!skip) {
                        uR[ridx] = fmaf(ex, dv, uR[ridx]);
                        pR[ridx] = fmaf(m, x, pR[ridx]);
                        if (!diag) {
                            int cidx = nt * 2 + e;
                            uC[cidx] = fmaf(ex, dTv, uC[cidx]);
                            pC[cidx] = fmaf(m, x, pC[cidx]);
                        }
                    }
                }
            }
        }
    }
#pragma unroll
    for (int mt = 0; mt < 4; mt++)
#pragma unroll
        for (int h = 0; h < 2; h++) {
            int r = wr * 64 + mt * 16 + rq + h * 8;
            atomicAdd(&uRow[r], uR[mt * 2 + h]);
            atomicAdd(&pRow[r], pR[mt * 2 + h]);
        }
    if (!diag) {
#pragma unroll
        for (int nt = 0; nt < 4; nt++)
#pragma unroll
            for (int e = 0; e < 2; e++) {
                int cc = wc * 32 + nt * 8 + cq + e;
                atomicAdd(&uCol[cc], uC[nt * 2 + e]);
                atomicAdd(&pCol[cc], pC[nt * 2 + e]);
            }
    }
    __syncthreads();
    if (tid < 128) {
        atomicAdd(&g_u[i0 + tid], uRow[tid]);
        atomicAdd(&g_p[i0 + tid], pRow[tid]);
        if (!diag) {
            atomicAdd(&g_u[j0 + tid], uCol[tid]);
            atomicAdd(&g_p[j0 + tid], pCol[tid]);
        }
    }
}

// ---------------- K4: final reduction -----------------------------------------
__global__ void k_final(float* __restrict__ out) {
    __shared__ float red[512];
    int tid = threadIdx.x;
    float sum = 0.f;
    for (int i = tid; i < NTOT; i += 512) {
        float lp = g_p[i] / g_S[i & (BSZ - 1)] - logf(g_u[i]);
        sum += lp;
    }
    red[tid] = sum; __syncthreads();
    for (int st = 256; st > 0; st >>= 1) { if (tid < st) red[tid] += red[tid + st]; __syncthreads(); }
    if (tid == 0) out[0] = -red[0] / (float)NTOT;
}

// ---------------- entry --------------------------------------------------------
extern "C" void kernel_launch(void* const* d_in, const int* in_sizes, int n_in,
                              void* d_out, int out_size) {
    (void)in_sizes; (void)n_in; (void)out_size;
    const float* feats  = (const float*)d_in[0];
    const float* labels = (const float*)d_in[1];
    float* out = (float*)d_out;

    cudaFuncSetAttribute(k_main, cudaFuncAttributeMaxDynamicSharedMemorySize, DSMEM);

    k_prep  <<<769, 1024>>>(feats, labels);
    k_tab   <<<2048, 256>>>(labels);
    k_transp<<<1024, 256>>>();
    k_main  <<<528, 256, DSMEM>>>(labels);
    k_final <<<1, 512>>>(out);
}